// round 9
// baseline (speedup 1.0000x reference)
#include <cuda_runtime.h>
#include <cstdint>

#define NBATCH 8

// ------------------------- scratch (device globals) ------------------------
__device__ float g_x1[(size_t)NBATCH * 64 * 256 * 256];
__device__ float g_x2[(size_t)NBATCH * 128 * 128 * 128];
__device__ float g_x3[(size_t)NBATCH * 256 * 64 * 64];
__device__ float g_x4[(size_t)NBATCH * 512 * 32 * 32];
__device__ float g_h [(size_t)NBATCH * 64 * 256 * 256];   // dw / s2d scratch
__device__ float g_e [(size_t)NBATCH * 256 * 256 * 256];  // expand scratch
__device__ float g_d3[(size_t)NBATCH * 256 * 64 * 64];
__device__ float g_d2[(size_t)NBATCH * 128 * 128 * 128];
__device__ float g_d1[(size_t)NBATCH * 64 * 256 * 256];
__device__ float g_t [(size_t)NBATCH * 2 * 256 * 256];
__device__ float g_u [(size_t)NBATCH * 256 * 256];
__device__ float g_ux[(size_t)NBATCH * 256 * 256];
__device__ float g_uy[(size_t)NBATCH * 256 * 256];
__device__ float g_mn[NBATCH];
__device__ float g_ps[NBATCH * 32];    // mean partials
__device__ float g_wt[1024 * 512];     // up-weight transpose
__device__ float g_wd[512 * 1024];     // down-weight reorder
__device__ float g_wdw[2 * 49 * 512];  // dw-weight transpose
__device__ float g_wh[9 * 64];         // head weight transpose
__device__ float g_wtl[2 * 9 * 64];    // tail weight transpose

// ----------------------------- PTX helpers ---------------------------------
__device__ __forceinline__ uint32_t smem_u32(const void* p) {
    uint32_t a;
    asm("{ .reg .u64 t; cvta.to.shared.u64 t, %1; cvt.u32.u64 %0, t; }" : "=r"(a) : "l"(p));
    return a;
}
__device__ __forceinline__ void cp16(uint32_t dst, const void* src) {
    asm volatile("cp.async.cg.shared.global [%0], [%1], 16;" :: "r"(dst), "l"(src));
}
__device__ __forceinline__ void cp_commit() {
    asm volatile("cp.async.commit_group;" ::: "memory");
}
template <int N>
__device__ __forceinline__ void cp_wait() {
    asm volatile("cp.async.wait_group %0;" :: "n"(N) : "memory");
}
__device__ __forceinline__ void mma8(float* c, const uint32_t* a, const uint32_t* b) {
    asm volatile(
        "mma.sync.aligned.m16n8k8.row.col.f32.tf32.tf32.f32 "
        "{%0,%1,%2,%3}, {%4,%5,%6,%7}, {%8,%9}, {%0,%1,%2,%3};"
        : "+f"(c[0]), "+f"(c[1]), "+f"(c[2]), "+f"(c[3])
        : "r"(a[0]), "r"(a[1]), "r"(a[2]), "r"(a[3]), "r"(b[0]), "r"(b[1]));
}
// split x into hi (tf32, round-to-nearest) and lo (residual, raw fp32 bits)
__device__ __forceinline__ void tf32_split(float v, uint32_t& hi, uint32_t& lo) {
    asm("cvt.rna.tf32.f32 %0, %1;" : "=r"(hi) : "f"(v));
    lo = __float_as_uint(v - __uint_as_float(hi));
}

// ------------------------------ 3xTF32 MMA GEMM -----------------------------
// C[row,n] = epi( sum_k A[row,k]*B[n,k] ); rows = NHWC pixels (NBATCH*H*W).
// Tile: 128 x BN x 32, 8 warps. EPI: 0 relu, 1 +Base, 2 plain,
// 3 pixel-shuffle up-scatter + skip add (Base=skip; wsh=log2(W_lo); Cout).
template <int BN, int EPI>
__global__ __launch_bounds__(256) void mma_gemm(
    const float* __restrict__ A, const float* __restrict__ B,
    float* __restrict__ Cp, const float* __restrict__ Base,
    int K, int Ntot, int wsh, int Cout)
{
    extern __shared__ float sm[];
    float* As = sm;                    // [2][128][36]
    float* Bs = sm + 2 * 128 * 36;     // [2][BN][36]
    const uint32_t sbase = smem_u32(sm);
    constexpr uint32_t BOFF = 2u * 128u * 36u * 4u;

    const int tid = threadIdx.x, wid = tid >> 5, lid = tid & 31;
    const int g = lid >> 2, tig = lid & 3;
    constexpr int MF = (BN == 128) ? 4 : 2;
    const int m0w = (BN == 128) ? (wid >> 2) * 64 : (wid >> 1) * 32;
    const int n0w = (BN == 128) ? (wid & 3) * 32 : (wid & 1) * 32;
    const int m0 = blockIdx.x * 128, n0 = blockIdx.y * BN;

    const float* Ag = A + (size_t)m0 * K;
    const float* Bg = B + (size_t)n0 * K;

    float acc[MF][4][4];
#pragma unroll
    for (int i = 0; i < MF; i++)
#pragma unroll
        for (int j = 0; j < 4; j++)
#pragma unroll
            for (int e = 0; e < 4; e++) acc[i][j][e] = 0.f;

    const int nc = K >> 5;

    // prefetch chunk 0 into buf 0
    {
#pragma unroll
        for (int i = 0; i < 4; i++) {
            int idx = tid + i * 256, r = idx >> 3, q = idx & 7;
            cp16(sbase + (uint32_t)(r * 36 + q * 4) * 4, Ag + (size_t)r * K + q * 4);
        }
#pragma unroll
        for (int i = 0; i < BN / 32; i++) {
            int idx = tid + i * 256, r = idx >> 3, q = idx & 7;
            cp16(sbase + BOFF + (uint32_t)(r * 36 + q * 4) * 4, Bg + (size_t)r * K + q * 4);
        }
        cp_commit();
    }

    for (int ck = 0; ck < nc; ck++) {
        const int buf = ck & 1;
        if (ck + 1 < nc) {
            const int nb = buf ^ 1;
            const float* Ab = Ag + (ck + 1) * 32;
#pragma unroll
            for (int i = 0; i < 4; i++) {
                int idx = tid + i * 256, r = idx >> 3, q = idx & 7;
                cp16(sbase + (uint32_t)(nb * 128 * 36 + r * 36 + q * 4) * 4,
                     Ab + (size_t)r * K + q * 4);
            }
            const float* Bb = Bg + (ck + 1) * 32;
#pragma unroll
            for (int i = 0; i < BN / 32; i++) {
                int idx = tid + i * 256, r = idx >> 3, q = idx & 7;
                cp16(sbase + BOFF + (uint32_t)(nb * BN * 36 + r * 36 + q * 4) * 4,
                     Bb + (size_t)r * K + q * 4);
            }
            cp_commit();
            cp_wait<1>();
        } else {
            cp_wait<0>();
        }
        __syncthreads();

        const float* Ab = As + buf * 128 * 36;
        const float* Bb = Bs + buf * BN * 36;
#pragma unroll
        for (int s = 0; s < 4; s++) {
            const int k = s * 8;
            uint32_t ah[MF][4], al[MF][4], bh[4][2], bl[4][2];
#pragma unroll
            for (int mf = 0; mf < MF; mf++) {
                const float* ap = Ab + (m0w + mf * 16 + g) * 36 + k + tig;
                tf32_split(ap[0],          ah[mf][0], al[mf][0]);
                tf32_split(ap[8 * 36],     ah[mf][1], al[mf][1]);
                tf32_split(ap[4],          ah[mf][2], al[mf][2]);
                tf32_split(ap[8 * 36 + 4], ah[mf][3], al[mf][3]);
            }
#pragma unroll
            for (int nf = 0; nf < 4; nf++) {
                const float* bp = Bb + (n0w + nf * 8 + g) * 36 + k + tig;
                tf32_split(bp[0], bh[nf][0], bl[nf][0]);
                tf32_split(bp[4], bh[nf][1], bl[nf][1]);
            }
            // 3xTF32: hi*hi + hi*lo + lo*hi (lo*lo dropped, ~2^-22)
#pragma unroll
            for (int mf = 0; mf < MF; mf++)
#pragma unroll
                for (int nf = 0; nf < 4; nf++) {
                    mma8(acc[mf][nf], al[mf], bh[nf]);
                    mma8(acc[mf][nf], ah[mf], bl[nf]);
                    mma8(acc[mf][nf], ah[mf], bh[nf]);
                }
        }
        __syncthreads();
    }

    // ------------------------------ epilogue --------------------------------
#pragma unroll
    for (int mf = 0; mf < MF; mf++) {
        const int r0 = m0 + m0w + mf * 16 + g;
        const int r1 = r0 + 8;
#pragma unroll
        for (int nf = 0; nf < 4; nf++) {
            const int col = n0 + n0w + nf * 8 + tig * 2;
            if (EPI == 3) {
#pragma unroll
                for (int half = 0; half < 2; half++) {
                    const int row = half ? r1 : r0;
                    const int n = row >> (2 * wsh);
                    const int rem = row & ((1 << (2 * wsh)) - 1);
                    const int h = rem >> wsh, w = rem & ((1 << wsh) - 1);
#pragma unroll
                    for (int e = 0; e < 2; e++) {
                        const int c = col + e;
                        const int o = c >> 2, a = (c >> 1) & 1, b = c & 1;
                        size_t pix = ((size_t)n << (2 * wsh + 2))
                                   + (size_t)((2 * h + a) << (wsh + 1)) + 2 * w + b;
                        size_t adr = pix * Cout + o;
                        Cp[adr] = acc[mf][nf][half * 2 + e] + Base[adr];
                    }
                }
            } else {
                size_t off0 = (size_t)r0 * Ntot + col;
                size_t off1 = (size_t)r1 * Ntot + col;
                float2 v0 = make_float2(acc[mf][nf][0], acc[mf][nf][1]);
                float2 v1 = make_float2(acc[mf][nf][2], acc[mf][nf][3]);
                if (EPI == 0) {
                    v0.x = fmaxf(v0.x, 0.f); v0.y = fmaxf(v0.y, 0.f);
                    v1.x = fmaxf(v1.x, 0.f); v1.y = fmaxf(v1.y, 0.f);
                } else if (EPI == 1) {
                    float2 b0 = *(const float2*)(Base + off0);
                    float2 b1 = *(const float2*)(Base + off1);
                    v0.x += b0.x; v0.y += b0.y;
                    v1.x += b1.x; v1.y += b1.y;
                }
                *(float2*)(Cp + off0) = v0;
                *(float2*)(Cp + off1) = v1;
            }
        }
    }
}

// ------------------- depthwise 7x7 (NHWC, smem-tiled) -----------------------
__device__ __forceinline__ void f4fma(float4& a, float4 w, float4 x) {
    a.x += w.x * x.x; a.y += w.y * x.y; a.z += w.z * x.z; a.w += w.w * x.w;
}
// CTA: 16h x 32w pixels, one float4 channel group. 256 threads, 2 outputs each.
__global__ __launch_bounds__(256) void dw7_tile(
    const float4* __restrict__ x, const float4* __restrict__ wT4,
    float4* __restrict__ y, int C4, int H, int W)
{
    const int c4 = blockIdx.z % C4;
    const int n  = blockIdx.z / C4;
    const int h0 = blockIdx.y * 16, w0 = blockIdx.x * 32;

    __shared__ float4 xs[22][38];
    __shared__ float4 ws[49];

    const int tid = threadIdx.x;
    if (tid < 49) ws[tid] = wT4[tid * C4 + c4];

    const size_t pbase = (size_t)n * H * W;
    for (int i = tid; i < 22 * 38; i += 256) {
        int r = i / 38, cc = i % 38;
        int hh = h0 - 3 + r, ww = w0 - 3 + cc;
        float4 v = make_float4(0.f, 0.f, 0.f, 0.f);
        if ((unsigned)hh < (unsigned)H && (unsigned)ww < (unsigned)W)
            v = x[(pbase + (size_t)hh * W + ww) * C4 + c4];
        xs[r][cc] = v;
    }
    __syncthreads();

    const int ty = tid >> 4;          // 0..15
    const int tx = (tid & 15) * 2;    // 0..30
    float4 a0 = make_float4(0.f, 0.f, 0.f, 0.f);
    float4 a1 = make_float4(0.f, 0.f, 0.f, 0.f);
#pragma unroll
    for (int dy = 0; dy < 7; dy++) {
        float4 r[8];
#pragma unroll
        for (int j = 0; j < 8; j++) r[j] = xs[ty + dy][tx + j];
#pragma unroll
        for (int k = 0; k < 7; k++) {
            float4 wv = ws[dy * 7 + k];
            f4fma(a0, wv, r[k]);
            f4fma(a1, wv, r[k + 1]);
        }
    }
    size_t o = (pbase + (size_t)(h0 + ty) * W + (w0 + tx)) * C4 + c4;
    y[o] = a0;
    y[o + C4] = a1;
}

// --------------------------- weight prep ------------------------------------
__global__ void dwT2_k(const float* __restrict__ dw, float* __restrict__ o,
                       int C, int total) {
    int idx = blockIdx.x * blockDim.x + threadIdx.x;
    if (idx >= total) return;
    int b = idx / (49 * C), r = idx % (49 * C);
    int tap = r / C, c = r % C;
    o[idx] = dw[(size_t)b * C * 49 + c * 49 + tap];
}
__global__ void wheadT_k(const float* __restrict__ w, float* __restrict__ o) {
    int idx = blockIdx.x * blockDim.x + threadIdx.x;
    if (idx >= 576) return;
    int tap = idx / 64, oc = idx % 64;
    o[idx] = w[oc * 9 + tap];
}
__global__ void wtailT_k(const float* __restrict__ w, float* __restrict__ o) {
    int idx = blockIdx.x * blockDim.x + threadIdx.x;
    if (idx >= 1152) return;
    int oc = idx / 576, r = idx % 576;
    int tap = r / 64, c = r % 64;
    o[oc * 576 + tap * 64 + c] = w[(oc * 64 + c) * 9 + tap];
}
__global__ void wdnR_k(const float* __restrict__ w, float* __restrict__ o,
                       int Ci, int total) {
    int idx = blockIdx.x * blockDim.x + threadIdx.x;
    if (idx >= total) return;
    int K4 = 4 * Ci;
    int co = idx / K4, k = idx % K4;
    int ab = k / Ci, ci = k % Ci;
    o[idx] = w[(size_t)co * K4 + ci * 4 + ab];
}
__global__ void wupT_k(const float* __restrict__ w, float* __restrict__ o,
                       int Ci, int M, int total) {
    int idx = blockIdx.x * blockDim.x + threadIdx.x;
    if (idx >= total) return;
    int ci = idx % Ci, m = idx / Ci;
    o[idx] = w[(size_t)ci * M + m];
}

// ----------------------- space-to-depth (NHWC, ab-major K) ------------------
__global__ void s2d_k(const float* __restrict__ x, float* __restrict__ o,
                      int Ci, int Ho, int Wo, int total)
{
    int idx = blockIdx.x * blockDim.x + threadIdx.x;
    if (idx >= total) return;
    const int Ci4 = Ci >> 2;
    int ci4 = idx % Ci4;
    int t = idx / Ci4;
    int ab = t & 3; t >>= 2;
    int wo = t % Wo; t /= Wo;
    int ho = t % Ho;
    int n = t / Ho;
    int a = ab >> 1, bq = ab & 1;
    int Wi = 2 * Wo;
    float4 v = *(const float4*)(x
        + ((size_t)(n * 2 * Ho + 2 * ho + a) * Wi + 2 * wo + bq) * Ci + ci4 * 4);
    *(float4*)(o + ((size_t)((n * Ho + ho) * Wo + wo)) * 4 * Ci
               + (size_t)ab * Ci + ci4 * 4) = v;
}

// ------------------------------ head / tail ---------------------------------
__global__ void head_k(const float* __restrict__ x0, const float* __restrict__ wT,
                       float* __restrict__ y, int total)
{
    int idx = blockIdx.x * blockDim.x + threadIdx.x;
    if (idx >= total) return;
    int o4 = idx & 15;
    int p = idx >> 4;
    int hw = p & 65535, n = p >> 16;
    int h = hw >> 8, w = hw & 255;
    const float* xp = x0 + (size_t)n * 65536;
    float4 acc = make_float4(0.f, 0.f, 0.f, 0.f);
#pragma unroll
    for (int dy = 0; dy < 3; dy++) {
        int yy = h + dy - 1;
        if ((unsigned)yy >= 256u) continue;
#pragma unroll
        for (int dx = 0; dx < 3; dx++) {
            int xx = w + dx - 1;
            if ((unsigned)xx >= 256u) continue;
            float xv = xp[yy * 256 + xx];
            float4 wv = *(const float4*)(wT + (dy * 3 + dx) * 64 + o4 * 4);
            acc.x += xv * wv.x; acc.y += xv * wv.y;
            acc.z += xv * wv.z; acc.w += xv * wv.w;
        }
    }
    *(float4*)(y + (size_t)p * 64 + o4 * 4) = acc;
}

__global__ void tail_k(const float* __restrict__ x, const float* __restrict__ wt,
                       float* __restrict__ T, int total)
{
    int idx = blockIdx.x * blockDim.x + threadIdx.x;
    if (idx >= total) return;
    int n = idx >> 16, hw = idx & 65535;
    int h = hw >> 8, w = hw & 255;
    const float* xn = x + (size_t)n * 65536 * 64;
    float a0 = 0.f, a1 = 0.f;
    for (int dy = 0; dy < 3; dy++) {
        int yy = h + dy - 1;
        if ((unsigned)yy >= 256u) continue;
        for (int dx = 0; dx < 3; dx++) {
            int xx = w + dx - 1;
            if ((unsigned)xx >= 256u) continue;
            int tap = dy * 3 + dx;
            const float* xp = xn + ((size_t)yy * 256 + xx) * 64;
            const float* w0p = wt + tap * 64;
            const float* w1p = wt + 576 + tap * 64;
#pragma unroll
            for (int c4 = 0; c4 < 16; c4++) {
                float4 xv = *(const float4*)(xp + c4 * 4);
                float4 w0 = *(const float4*)(w0p + c4 * 4);
                float4 w1 = *(const float4*)(w1p + c4 * 4);
                a0 += xv.x * w0.x + xv.y * w0.y + xv.z * w0.z + xv.w * w0.w;
                a1 += xv.x * w1.x + xv.y * w1.y + xv.z * w1.z + xv.w * w1.w;
            }
        }
    }
    T[(size_t)n * 131072 + hw] = a0;
    T[(size_t)n * 131072 + 65536 + hw] = a1;
}

// ------------------------------ epilogue ------------------------------------
__global__ void mean1_k(const float* __restrict__ tail, float* __restrict__ ps)
{
    __shared__ float s[256];
    int n = blockIdx.x, j = blockIdx.y;
    const float* p = tail + (size_t)n * 131072 + j * 2048;
    float acc = 0.f;
    for (int i = threadIdx.x; i < 2048; i += 256) acc += p[i];
    s[threadIdx.x] = acc;
    __syncthreads();
    for (int st = 128; st > 0; st >>= 1) {
        if (threadIdx.x < st) s[threadIdx.x] += s[threadIdx.x + st];
        __syncthreads();
    }
    if (threadIdx.x == 0) ps[n * 32 + j] = s[0];
}
__global__ void mean2_k(const float* __restrict__ ps, float* __restrict__ mean)
{
    int t = threadIdx.x;
    if (t < NBATCH) {
        float s = 0.f;
        for (int j = 0; j < 32; j++) s += ps[t * 32 + j];
        mean[t] = s * (1.f / 65536.f);
    }
}

__global__ void finalize1(const float* __restrict__ tail, const float* __restrict__ x0,
                          const float* __restrict__ mean, float* __restrict__ out,
                          float* __restrict__ u)
{
    int idx = blockIdx.x * blockDim.x + threadIdx.x;
    if (idx >= 524288) return;
    int n = idx >> 16, p = idx & 65535;
    float nd = tail[(size_t)n * 131072 + 65536 + p];
    out[idx] = mean[n];
    out[524288 + idx] = nd;
    u[idx] = nd + x0[idx];
}

__device__ __forceinline__ float gx_(const float* u, int h, int w) {
    if (w == 0)   return u[h * 256 + 1] - u[h * 256];
    if (w == 255) return u[h * 256 + 255] - u[h * 256 + 254];
    return 0.5f * (u[h * 256 + w + 1] - u[h * 256 + w - 1]);
}
__device__ __forceinline__ float gy_(const float* u, int h, int w) {
    if (h == 0)   return u[256 + w] - u[w];
    if (h == 255) return u[255 * 256 + w] - u[254 * 256 + w];
    return 0.5f * (u[(h + 1) * 256 + w] - u[(h - 1) * 256 + w]);
}

__global__ void grad_k(const float* __restrict__ u, float* __restrict__ ux,
                       float* __restrict__ uy)
{
    int idx = blockIdx.x * blockDim.x + threadIdx.x;
    if (idx >= 524288) return;
    int n = idx >> 16, p = idx & 65535;
    int h = p >> 8, w = p & 255;
    const float* up = u + (size_t)n * 65536;
    ux[idx] = gx_(up, h, w);
    uy[idx] = gy_(up, h, w);
}

__global__ void curv_k(const float* __restrict__ ux, const float* __restrict__ uy,
                       float* __restrict__ out)
{
    int idx = blockIdx.x * blockDim.x + threadIdx.x;
    if (idx >= 524288) return;
    int n = idx >> 16, p = idx & 65535;
    int h = p >> 8, w = p & 255;
    const float* uxp = ux + (size_t)n * 65536;
    const float* uyp = uy + (size_t)n * 65536;
    float uxx = gx_(uxp, h, w);
    float uyy = gy_(uyp, h, w);
    float uxy = gy_(uxp, h, w);
    float a = uxp[h * 256 + w], b = uyp[h * 256 + w];
    float den = 1.f + a * a + b * b;
    out[idx] = (uxx * uyy - uxy * uxy) / (den * den);
}

// ------------------------------ host side -----------------------------------
static inline int ceil_div(int a, int b) { return (a + b - 1) / b; }
static inline int smszA(int bn) { return (2 * 128 * 36 + 2 * bn * 36) * 4; }

static void run_stage(const float* dwW, const float* w1, const float* w2,
                      float* x, float* hbuf, float* ebuf, float* wdwT,
                      int C, int H, int W)
{
    int P = H * W, rows = NBATCH * P, tiles = rows / 128;
    int C4 = C / 4;
    int dwtot = 2 * 49 * C;
    dwT2_k<<<ceil_div(dwtot, 256), 256>>>(dwW, wdwT, C, dwtot);
    dim3 gdw(W / 32, H / 16, NBATCH * C4);
    for (int b = 0; b < 2; b++) {
        dw7_tile<<<gdw, 256>>>((const float4*)x,
                               (const float4*)(wdwT + b * 49 * C),
                               (float4*)hbuf, C4, H, W);
        mma_gemm<128, 0><<<dim3(tiles, (4 * C) / 128), 256, smszA(128)>>>(
            hbuf, w1 + (size_t)b * 4 * C * C, ebuf, ebuf, C, 4 * C, 0, 0);
        const float* w2b = w2 + (size_t)b * C * 4 * C;
        if (C == 64)
            mma_gemm<64, 1><<<dim3(tiles, 1), 256, smszA(64)>>>(
                ebuf, w2b, x, x, 4 * C, C, 0, 0);
        else
            mma_gemm<128, 1><<<dim3(tiles, C / 128), 256, smszA(128)>>>(
                ebuf, w2b, x, x, 4 * C, C, 0, 0);
    }
}

static void run_down(const float* x, const float* wdn, float* hbuf, float* wd,
                     float* y, int Ci, int Co, int Ho, int Wo)
{
    int K = 4 * Ci;
    int wtot = Co * K;
    wdnR_k<<<ceil_div(wtot, 256), 256>>>(wdn, wd, Ci, wtot);
    int s2dtot = NBATCH * Ho * Wo * 4 * (Ci / 4);
    s2d_k<<<ceil_div(s2dtot, 256), 256>>>(x, hbuf, Ci, Ho, Wo, s2dtot);
    int tiles = NBATCH * Ho * Wo / 128;
    mma_gemm<128, 2><<<dim3(tiles, Co / 128), 256, smszA(128)>>>(
        hbuf, wd, y, y, K, Co, 0, 0);
}

static void run_up(const float* x, const float* wup, const float* skip, float* y,
                   float* wt, int Ci, int Co, int wsh)
{
    int M = Co * 4;
    int wtot = M * Ci;
    wupT_k<<<ceil_div(wtot, 256), 256>>>(wup, wt, Ci, M, wtot);
    int P_lo = 1 << (2 * wsh);
    int tiles = NBATCH * P_lo / 128;
    mma_gemm<128, 3><<<dim3(tiles, M / 128), 256, smszA(128)>>>(
        x, wt, y, skip, Ci, M, wsh, Co);
}

extern "C" void kernel_launch(void* const* d_in, const int* in_sizes, int n_in,
                              void* d_out, int out_size)
{
    const float* x0      = (const float*)d_in[0];
    const float* w_head  = (const float*)d_in[1];
    const float* en1_dw  = (const float*)d_in[2];
    const float* en1_w1  = (const float*)d_in[3];
    const float* en1_w2  = (const float*)d_in[4];
    const float* w_down1 = (const float*)d_in[5];
    const float* en2_dw  = (const float*)d_in[6];
    const float* en2_w1  = (const float*)d_in[7];
    const float* en2_w2  = (const float*)d_in[8];
    const float* w_down2 = (const float*)d_in[9];
    const float* en3_dw  = (const float*)d_in[10];
    const float* en3_w1  = (const float*)d_in[11];
    const float* en3_w2  = (const float*)d_in[12];
    const float* w_down3 = (const float*)d_in[13];
    const float* body_dw = (const float*)d_in[14];
    const float* body_w1 = (const float*)d_in[15];
    const float* body_w2 = (const float*)d_in[16];
    const float* w_up3   = (const float*)d_in[17];
    const float* de3_dw  = (const float*)d_in[18];
    const float* de3_w1  = (const float*)d_in[19];
    const float* de3_w2  = (const float*)d_in[20];
    const float* w_up2   = (const float*)d_in[21];
    const float* de2_dw  = (const float*)d_in[22];
    const float* de2_w1  = (const float*)d_in[23];
    const float* de2_w2  = (const float*)d_in[24];
    const float* w_up1   = (const float*)d_in[25];
    const float* de1_dw  = (const float*)d_in[26];
    const float* de1_w1  = (const float*)d_in[27];
    const float* de1_w2  = (const float*)d_in[28];
    const float* w_tail  = (const float*)d_in[29];
    float* out = (float*)d_out;

    cudaFuncSetAttribute(mma_gemm<128, 0>, cudaFuncAttributeMaxDynamicSharedMemorySize, smszA(128));
    cudaFuncSetAttribute(mma_gemm<128, 1>, cudaFuncAttributeMaxDynamicSharedMemorySize, smszA(128));
    cudaFuncSetAttribute(mma_gemm<64, 1>,  cudaFuncAttributeMaxDynamicSharedMemorySize, smszA(64));
    cudaFuncSetAttribute(mma_gemm<128, 2>, cudaFuncAttributeMaxDynamicSharedMemorySize, smszA(128));
    cudaFuncSetAttribute(mma_gemm<128, 3>, cudaFuncAttributeMaxDynamicSharedMemorySize, smszA(128));

    float *X1, *X2, *X3, *X4, *H, *E, *D3, *D2, *D1, *T, *U, *UX, *UY, *MN, *PS, *WT, *WD, *WDW, *WH, *WTL;
    cudaGetSymbolAddress((void**)&X1, g_x1);
    cudaGetSymbolAddress((void**)&X2, g_x2);
    cudaGetSymbolAddress((void**)&X3, g_x3);
    cudaGetSymbolAddress((void**)&X4, g_x4);
    cudaGetSymbolAddress((void**)&H,  g_h);
    cudaGetSymbolAddress((void**)&E,  g_e);
    cudaGetSymbolAddress((void**)&D3, g_d3);
    cudaGetSymbolAddress((void**)&D2, g_d2);
    cudaGetSymbolAddress((void**)&D1, g_d1);
    cudaGetSymbolAddress((void**)&T,  g_t);
    cudaGetSymbolAddress((void**)&U,  g_u);
    cudaGetSymbolAddress((void**)&UX, g_ux);
    cudaGetSymbolAddress((void**)&UY, g_uy);
    cudaGetSymbolAddress((void**)&MN, g_mn);
    cudaGetSymbolAddress((void**)&PS, g_ps);
    cudaGetSymbolAddress((void**)&WT, g_wt);
    cudaGetSymbolAddress((void**)&WD, g_wd);
    cudaGetSymbolAddress((void**)&WDW, g_wdw);
    cudaGetSymbolAddress((void**)&WH, g_wh);
    cudaGetSymbolAddress((void**)&WTL, g_wtl);

    // ---------------- encoder (NHWC) ----------------
    wheadT_k<<<3, 256>>>(w_head, WH);
    {
        int total = NBATCH * 65536 * 16;
        head_k<<<ceil_div(total, 256), 256>>>(x0, WH, X1, total);
    }
    run_stage(en1_dw, en1_w1, en1_w2, X1, H, E, WDW, 64, 256, 256);

    run_down(X1, w_down1, H, WD, X2, 64, 128, 128, 128);
    run_stage(en2_dw, en2_w1, en2_w2, X2, H, E, WDW, 128, 128, 128);

    run_down(X2, w_down2, H, WD, X3, 128, 256, 64, 64);
    run_stage(en3_dw, en3_w1, en3_w2, X3, H, E, WDW, 256, 64, 64);

    run_down(X3, w_down3, H, WD, X4, 256, 512, 32, 32);
    run_stage(body_dw, body_w1, body_w2, X4, H, E, WDW, 512, 32, 32);

    // ---------------- decoder ----------------
    run_up(X4, w_up3, X3, D3, WT, 512, 256, 5);
    run_stage(de3_dw, de3_w1, de3_w2, D3, H, E, WDW, 256, 64, 64);

    run_up(D3, w_up2, X2, D2, WT, 256, 128, 6);
    run_stage(de2_dw, de2_w1, de2_w2, D2, H, E, WDW, 128, 128, 128);

    run_up(D2, w_up1, X1, D1, WT, 128, 64, 7);
    run_stage(de1_dw, de1_w1, de1_w2, D1, H, E, WDW, 64, 256, 256);

    wtailT_k<<<5, 256>>>(w_tail, WTL);
    {
        int total = NBATCH * 65536;
        tail_k<<<ceil_div(total, 256), 256>>>(D1, WTL, T, total);
    }

    // ---------------- epilogue ----------------
    mean1_k<<<dim3(NBATCH, 32), 256>>>(T, PS);
    mean2_k<<<1, 32>>>(PS, MN);
    finalize1<<<2048, 256>>>(T, x0, MN, out, U);
    grad_k<<<2048, 256>>>(U, UX, UY);
    curv_k<<<2048, 256>>>(UX, UY, out + 1048576);
}

// round 10
// speedup vs baseline: 1.6050x; 1.6050x over previous
#include <cuda_runtime.h>
#include <cstdint>

#define NBATCH 8

// ------------------------- scratch (device globals) ------------------------
__device__ float g_x1[(size_t)NBATCH * 64 * 256 * 256];
__device__ float g_x2[(size_t)NBATCH * 128 * 128 * 128];
__device__ float g_x3[(size_t)NBATCH * 256 * 64 * 64];
__device__ float g_x4[(size_t)NBATCH * 512 * 32 * 32];
__device__ float g_h [(size_t)NBATCH * 64 * 256 * 256];   // dw / s2d scratch
__device__ float g_e [(size_t)NBATCH * 256 * 256 * 256];  // expand scratch
__device__ float g_d3[(size_t)NBATCH * 256 * 64 * 64];
__device__ float g_d2[(size_t)NBATCH * 128 * 128 * 128];
__device__ float g_d1[(size_t)NBATCH * 64 * 256 * 256];
__device__ float g_t [(size_t)NBATCH * 2 * 256 * 256];
__device__ float g_u [(size_t)NBATCH * 256 * 256];
__device__ float g_ux[(size_t)NBATCH * 256 * 256];
__device__ float g_uy[(size_t)NBATCH * 256 * 256];
__device__ float g_mn[NBATCH];
__device__ float g_ps[NBATCH * 32];    // mean partials
__device__ float g_wt[1024 * 512];     // up-weight transpose
__device__ float g_wd[512 * 1024];     // down-weight reorder
__device__ float g_wdw[2 * 49 * 512];  // dw-weight transpose
__device__ float g_wh[9 * 64];         // head weight transpose
__device__ float g_wtl[2 * 9 * 64];    // tail weight transpose

// ----------------------------- PTX helpers ---------------------------------
__device__ __forceinline__ uint32_t smem_u32(const void* p) {
    uint32_t a;
    asm("{ .reg .u64 t; cvta.to.shared.u64 t, %1; cvt.u32.u64 %0, t; }" : "=r"(a) : "l"(p));
    return a;
}
__device__ __forceinline__ void cp16(uint32_t dst, const void* src) {
    asm volatile("cp.async.cg.shared.global [%0], [%1], 16;" :: "r"(dst), "l"(src));
}
__device__ __forceinline__ void cp_commit() {
    asm volatile("cp.async.commit_group;" ::: "memory");
}
template <int N>
__device__ __forceinline__ void cp_wait() {
    asm volatile("cp.async.wait_group %0;" :: "n"(N) : "memory");
}
__device__ __forceinline__ void mma8(float* c, const uint32_t* a, const uint32_t* b) {
    asm volatile(
        "mma.sync.aligned.m16n8k8.row.col.f32.tf32.tf32.f32 "
        "{%0,%1,%2,%3}, {%4,%5,%6,%7}, {%8,%9}, {%0,%1,%2,%3};"
        : "+f"(c[0]), "+f"(c[1]), "+f"(c[2]), "+f"(c[3])
        : "r"(a[0]), "r"(a[1]), "r"(a[2]), "r"(a[3]), "r"(b[0]), "r"(b[1]));
}
// split x into hi (tf32, round-to-nearest) and lo (residual, raw fp32 bits)
__device__ __forceinline__ void tf32_split(float v, uint32_t& hi, uint32_t& lo) {
    asm("cvt.rna.tf32.f32 %0, %1;" : "=r"(hi) : "f"(v));
    lo = __float_as_uint(v - __uint_as_float(hi));
}

// ------------------------------ 3xTF32 MMA GEMM -----------------------------
// C[row,n] = epi( sum_k A[row,k]*B[n,k] ); rows = NHWC pixels (NBATCH*H*W).
// Tile: 128 x BN x 32, 8 warps. EPI: 0 relu, 1 +Base, 2 plain,
// 3 pixel-shuffle up-scatter + skip add (Base=skip; wsh=log2(W_lo); Cout).
template <int BN, int EPI>
__global__ __launch_bounds__(256) void mma_gemm(
    const float* __restrict__ A, const float* __restrict__ B,
    float* __restrict__ Cp, const float* __restrict__ Base,
    int K, int Ntot, int wsh, int Cout)
{
    extern __shared__ float sm[];
    float* As = sm;                    // [2][128][36]
    float* Bs = sm + 2 * 128 * 36;     // [2][BN][36]
    const uint32_t sbase = smem_u32(sm);
    constexpr uint32_t BOFF = 2u * 128u * 36u * 4u;

    const int tid = threadIdx.x, wid = tid >> 5, lid = tid & 31;
    const int g = lid >> 2, tig = lid & 3;
    constexpr int MF = (BN == 128) ? 4 : 2;
    const int m0w = (BN == 128) ? (wid >> 2) * 64 : (wid >> 1) * 32;
    const int n0w = (BN == 128) ? (wid & 3) * 32 : (wid & 1) * 32;
    const int m0 = blockIdx.x * 128, n0 = blockIdx.y * BN;

    const float* Ag = A + (size_t)m0 * K;
    const float* Bg = B + (size_t)n0 * K;

    float acc[MF][4][4];
#pragma unroll
    for (int i = 0; i < MF; i++)
#pragma unroll
        for (int j = 0; j < 4; j++)
#pragma unroll
            for (int e = 0; e < 4; e++) acc[i][j][e] = 0.f;

    const int nc = K >> 5;

    // prefetch chunk 0 into buf 0
    {
#pragma unroll
        for (int i = 0; i < 4; i++) {
            int idx = tid + i * 256, r = idx >> 3, q = idx & 7;
            cp16(sbase + (uint32_t)(r * 36 + q * 4) * 4, Ag + (size_t)r * K + q * 4);
        }
#pragma unroll
        for (int i = 0; i < BN / 32; i++) {
            int idx = tid + i * 256, r = idx >> 3, q = idx & 7;
            cp16(sbase + BOFF + (uint32_t)(r * 36 + q * 4) * 4, Bg + (size_t)r * K + q * 4);
        }
        cp_commit();
    }

    for (int ck = 0; ck < nc; ck++) {
        const int buf = ck & 1;
        if (ck + 1 < nc) {
            const int nb = buf ^ 1;
            const float* Ab = Ag + (ck + 1) * 32;
#pragma unroll
            for (int i = 0; i < 4; i++) {
                int idx = tid + i * 256, r = idx >> 3, q = idx & 7;
                cp16(sbase + (uint32_t)(nb * 128 * 36 + r * 36 + q * 4) * 4,
                     Ab + (size_t)r * K + q * 4);
            }
            const float* Bb = Bg + (ck + 1) * 32;
#pragma unroll
            for (int i = 0; i < BN / 32; i++) {
                int idx = tid + i * 256, r = idx >> 3, q = idx & 7;
                cp16(sbase + BOFF + (uint32_t)(nb * BN * 36 + r * 36 + q * 4) * 4,
                     Bb + (size_t)r * K + q * 4);
            }
            cp_commit();
            cp_wait<1>();
        } else {
            cp_wait<0>();
        }
        __syncthreads();

        const float* Ab = As + buf * 128 * 36;
        const float* Bb = Bs + buf * BN * 36;
#pragma unroll
        for (int s = 0; s < 4; s++) {
            const int k = s * 8;
            uint32_t ah[MF][4], al[MF][4], bh[4][2], bl[4][2];
#pragma unroll
            for (int mf = 0; mf < MF; mf++) {
                const float* ap = Ab + (m0w + mf * 16 + g) * 36 + k + tig;
                tf32_split(ap[0],          ah[mf][0], al[mf][0]);
                tf32_split(ap[8 * 36],     ah[mf][1], al[mf][1]);
                tf32_split(ap[4],          ah[mf][2], al[mf][2]);
                tf32_split(ap[8 * 36 + 4], ah[mf][3], al[mf][3]);
            }
#pragma unroll
            for (int nf = 0; nf < 4; nf++) {
                const float* bp = Bb + (n0w + nf * 8 + g) * 36 + k + tig;
                tf32_split(bp[0], bh[nf][0], bl[nf][0]);
                tf32_split(bp[4], bh[nf][1], bl[nf][1]);
            }
            // 3xTF32: hi*hi + hi*lo + lo*hi (lo*lo dropped, ~2^-22)
#pragma unroll
            for (int mf = 0; mf < MF; mf++)
#pragma unroll
                for (int nf = 0; nf < 4; nf++) {
                    mma8(acc[mf][nf], al[mf], bh[nf]);
                    mma8(acc[mf][nf], ah[mf], bl[nf]);
                    mma8(acc[mf][nf], ah[mf], bh[nf]);
                }
        }
        __syncthreads();
    }

    // ------------------------------ epilogue --------------------------------
#pragma unroll
    for (int mf = 0; mf < MF; mf++) {
        const int r0 = m0 + m0w + mf * 16 + g;
        const int r1 = r0 + 8;
#pragma unroll
        for (int nf = 0; nf < 4; nf++) {
            const int col = n0 + n0w + nf * 8 + tig * 2;
            if (EPI == 3) {
#pragma unroll
                for (int half = 0; half < 2; half++) {
                    const int row = half ? r1 : r0;
                    const int n = row >> (2 * wsh);
                    const int rem = row & ((1 << (2 * wsh)) - 1);
                    const int h = rem >> wsh, w = rem & ((1 << wsh) - 1);
#pragma unroll
                    for (int e = 0; e < 2; e++) {
                        const int c = col + e;
                        const int o = c >> 2, a = (c >> 1) & 1, b = c & 1;
                        size_t pix = ((size_t)n << (2 * wsh + 2))
                                   + (size_t)((2 * h + a) << (wsh + 1)) + 2 * w + b;
                        size_t adr = pix * Cout + o;
                        Cp[adr] = acc[mf][nf][half * 2 + e] + Base[adr];
                    }
                }
            } else {
                size_t off0 = (size_t)r0 * Ntot + col;
                size_t off1 = (size_t)r1 * Ntot + col;
                float2 v0 = make_float2(acc[mf][nf][0], acc[mf][nf][1]);
                float2 v1 = make_float2(acc[mf][nf][2], acc[mf][nf][3]);
                if (EPI == 0) {
                    v0.x = fmaxf(v0.x, 0.f); v0.y = fmaxf(v0.y, 0.f);
                    v1.x = fmaxf(v1.x, 0.f); v1.y = fmaxf(v1.y, 0.f);
                } else if (EPI == 1) {
                    float2 b0 = *(const float2*)(Base + off0);
                    float2 b1 = *(const float2*)(Base + off1);
                    v0.x += b0.x; v0.y += b0.y;
                    v1.x += b1.x; v1.y += b1.y;
                }
                *(float2*)(Cp + off0) = v0;
                *(float2*)(Cp + off1) = v1;
            }
        }
    }
}

// ------------------------- depthwise 7x7 (NHWC) -----------------------------
__device__ __forceinline__ void f4fma(float4& a, float4 w, float4 x) {
    a.x += w.x * x.x; a.y += w.y * x.y; a.z += w.z * x.z; a.w += w.w * x.w;
}
__global__ __launch_bounds__(256) void dw7_nhwc(
    const float* __restrict__ x, const float* __restrict__ wT,
    float* __restrict__ y, int C, int H, int W, int total)
{
    int idx = blockIdx.x * blockDim.x + threadIdx.x;
    if (idx >= total) return;
    const int C4 = C >> 2;
    int c4 = idx % C4;
    int t = idx / C4;
    int w4 = t % (W >> 2); t /= (W >> 2);
    int h = t % H;
    int n = t / H;
    int w0 = w4 * 4;
    const float* xb = x + (size_t)n * H * W * C + (size_t)c4 * 4;
    float4 acc[4];
#pragma unroll
    for (int j = 0; j < 4; j++) acc[j] = make_float4(0.f, 0.f, 0.f, 0.f);
    for (int dy = 0; dy < 7; dy++) {
        int hy = h + dy - 3;
        if ((unsigned)hy >= (unsigned)H) continue;
        const float* xrow = xb + (size_t)hy * W * C;
        float4 wv[7];
#pragma unroll
        for (int k = 0; k < 7; k++)
            wv[k] = *(const float4*)(wT + (size_t)(dy * 7 + k) * C + c4 * 4);
#pragma unroll
        for (int dx = 0; dx < 10; dx++) {
            int wx = w0 + dx - 3;
            if ((unsigned)wx >= (unsigned)W) continue;
            float4 xv = *(const float4*)(xrow + (size_t)wx * C);
#pragma unroll
            for (int j = 0; j < 4; j++) {
                int k = dx - j;
                if (k >= 0 && k < 7) f4fma(acc[j], wv[k], xv);
            }
        }
    }
    float* yb = y + ((size_t)(n * H + h) * W + w0) * C + c4 * 4;
#pragma unroll
    for (int j = 0; j < 4; j++) *(float4*)(yb + (size_t)j * C) = acc[j];
}

// --------------------------- weight prep ------------------------------------
__global__ void dwT2_k(const float* __restrict__ dw, float* __restrict__ o,
                       int C, int total) {
    int idx = blockIdx.x * blockDim.x + threadIdx.x;
    if (idx >= total) return;
    int b = idx / (49 * C), r = idx % (49 * C);
    int tap = r / C, c = r % C;
    o[idx] = dw[(size_t)b * C * 49 + c * 49 + tap];
}
__global__ void wheadT_k(const float* __restrict__ w, float* __restrict__ o) {
    int idx = blockIdx.x * blockDim.x + threadIdx.x;
    if (idx >= 576) return;
    int tap = idx / 64, oc = idx % 64;
    o[idx] = w[oc * 9 + tap];
}
__global__ void wtailT_k(const float* __restrict__ w, float* __restrict__ o) {
    int idx = blockIdx.x * blockDim.x + threadIdx.x;
    if (idx >= 1152) return;
    int oc = idx / 576, r = idx % 576;
    int tap = r / 64, c = r % 64;
    o[oc * 576 + tap * 64 + c] = w[(oc * 64 + c) * 9 + tap];
}
__global__ void wdnR_k(const float* __restrict__ w, float* __restrict__ o,
                       int Ci, int total) {
    int idx = blockIdx.x * blockDim.x + threadIdx.x;
    if (idx >= total) return;
    int K4 = 4 * Ci;
    int co = idx / K4, k = idx % K4;
    int ab = k / Ci, ci = k % Ci;
    o[idx] = w[(size_t)co * K4 + ci * 4 + ab];
}
__global__ void wupT_k(const float* __restrict__ w, float* __restrict__ o,
                       int Ci, int M, int total) {
    int idx = blockIdx.x * blockDim.x + threadIdx.x;
    if (idx >= total) return;
    int ci = idx % Ci, m = idx / Ci;
    o[idx] = w[(size_t)ci * M + m];
}

// ----------------------- space-to-depth (NHWC, ab-major K) ------------------
__global__ void s2d_k(const float* __restrict__ x, float* __restrict__ o,
                      int Ci, int Ho, int Wo, int total)
{
    int idx = blockIdx.x * blockDim.x + threadIdx.x;
    if (idx >= total) return;
    const int Ci4 = Ci >> 2;
    int ci4 = idx % Ci4;
    int t = idx / Ci4;
    int ab = t & 3; t >>= 2;
    int wo = t % Wo; t /= Wo;
    int ho = t % Ho;
    int n = t / Ho;
    int a = ab >> 1, bq = ab & 1;
    int Wi = 2 * Wo;
    float4 v = *(const float4*)(x
        + ((size_t)(n * 2 * Ho + 2 * ho + a) * Wi + 2 * wo + bq) * Ci + ci4 * 4);
    *(float4*)(o + ((size_t)((n * Ho + ho) * Wo + wo)) * 4 * Ci
               + (size_t)ab * Ci + ci4 * 4) = v;
}

// ------------------------------ head / tail ---------------------------------
__global__ void head_k(const float* __restrict__ x0, const float* __restrict__ wT,
                       float* __restrict__ y, int total)
{
    int idx = blockIdx.x * blockDim.x + threadIdx.x;
    if (idx >= total) return;
    int o4 = idx & 15;
    int p = idx >> 4;
    int hw = p & 65535, n = p >> 16;
    int h = hw >> 8, w = hw & 255;
    const float* xp = x0 + (size_t)n * 65536;
    float4 acc = make_float4(0.f, 0.f, 0.f, 0.f);
#pragma unroll
    for (int dy = 0; dy < 3; dy++) {
        int yy = h + dy - 1;
        if ((unsigned)yy >= 256u) continue;
#pragma unroll
        for (int dx = 0; dx < 3; dx++) {
            int xx = w + dx - 1;
            if ((unsigned)xx >= 256u) continue;
            float xv = xp[yy * 256 + xx];
            float4 wv = *(const float4*)(wT + (dy * 3 + dx) * 64 + o4 * 4);
            acc.x += xv * wv.x; acc.y += xv * wv.y;
            acc.z += xv * wv.z; acc.w += xv * wv.w;
        }
    }
    *(float4*)(y + (size_t)p * 64 + o4 * 4) = acc;
}

__global__ void tail_k(const float* __restrict__ x, const float* __restrict__ wt,
                       float* __restrict__ T, int total)
{
    int idx = blockIdx.x * blockDim.x + threadIdx.x;
    if (idx >= total) return;
    int n = idx >> 16, hw = idx & 65535;
    int h = hw >> 8, w = hw & 255;
    const float* xn = x + (size_t)n * 65536 * 64;
    float a0 = 0.f, a1 = 0.f;
    for (int dy = 0; dy < 3; dy++) {
        int yy = h + dy - 1;
        if ((unsigned)yy >= 256u) continue;
        for (int dx = 0; dx < 3; dx++) {
            int xx = w + dx - 1;
            if ((unsigned)xx >= 256u) continue;
            int tap = dy * 3 + dx;
            const float* xp = xn + ((size_t)yy * 256 + xx) * 64;
            const float* w0p = wt + tap * 64;
            const float* w1p = wt + 576 + tap * 64;
#pragma unroll
            for (int c4 = 0; c4 < 16; c4++) {
                float4 xv = *(const float4*)(xp + c4 * 4);
                float4 w0 = *(const float4*)(w0p + c4 * 4);
                float4 w1 = *(const float4*)(w1p + c4 * 4);
                a0 += xv.x * w0.x + xv.y * w0.y + xv.z * w0.z + xv.w * w0.w;
                a1 += xv.x * w1.x + xv.y * w1.y + xv.z * w1.z + xv.w * w1.w;
            }
        }
    }
    T[(size_t)n * 131072 + hw] = a0;
    T[(size_t)n * 131072 + 65536 + hw] = a1;
}

// ------------------------------ epilogue ------------------------------------
__global__ void mean1_k(const float* __restrict__ tail, float* __restrict__ ps)
{
    __shared__ float s[256];
    int n = blockIdx.x, j = blockIdx.y;
    const float* p = tail + (size_t)n * 131072 + j * 2048;
    float acc = 0.f;
    for (int i = threadIdx.x; i < 2048; i += 256) acc += p[i];
    s[threadIdx.x] = acc;
    __syncthreads();
    for (int st = 128; st > 0; st >>= 1) {
        if (threadIdx.x < st) s[threadIdx.x] += s[threadIdx.x + st];
        __syncthreads();
    }
    if (threadIdx.x == 0) ps[n * 32 + j] = s[0];
}
__global__ void mean2_k(const float* __restrict__ ps, float* __restrict__ mean)
{
    int t = threadIdx.x;
    if (t < NBATCH) {
        float s = 0.f;
        for (int j = 0; j < 32; j++) s += ps[t * 32 + j];
        mean[t] = s * (1.f / 65536.f);
    }
}

__global__ void finalize1(const float* __restrict__ tail, const float* __restrict__ x0,
                          const float* __restrict__ mean, float* __restrict__ out,
                          float* __restrict__ u)
{
    int idx = blockIdx.x * blockDim.x + threadIdx.x;
    if (idx >= 524288) return;
    int n = idx >> 16, p = idx & 65535;
    float nd = tail[(size_t)n * 131072 + 65536 + p];
    out[idx] = mean[n];
    out[524288 + idx] = nd;
    u[idx] = nd + x0[idx];
}

__device__ __forceinline__ float gx_(const float* u, int h, int w) {
    if (w == 0)   return u[h * 256 + 1] - u[h * 256];
    if (w == 255) return u[h * 256 + 255] - u[h * 256 + 254];
    return 0.5f * (u[h * 256 + w + 1] - u[h * 256 + w - 1]);
}
__device__ __forceinline__ float gy_(const float* u, int h, int w) {
    if (h == 0)   return u[256 + w] - u[w];
    if (h == 255) return u[255 * 256 + w] - u[254 * 256 + w];
    return 0.5f * (u[(h + 1) * 256 + w] - u[(h - 1) * 256 + w]);
}

__global__ void grad_k(const float* __restrict__ u, float* __restrict__ ux,
                       float* __restrict__ uy)
{
    int idx = blockIdx.x * blockDim.x + threadIdx.x;
    if (idx >= 524288) return;
    int n = idx >> 16, p = idx & 65535;
    int h = p >> 8, w = p & 255;
    const float* up = u + (size_t)n * 65536;
    ux[idx] = gx_(up, h, w);
    uy[idx] = gy_(up, h, w);
}

__global__ void curv_k(const float* __restrict__ ux, const float* __restrict__ uy,
                       float* __restrict__ out)
{
    int idx = blockIdx.x * blockDim.x + threadIdx.x;
    if (idx >= 524288) return;
    int n = idx >> 16, p = idx & 65535;
    int h = p >> 8, w = p & 255;
    const float* uxp = ux + (size_t)n * 65536;
    const float* uyp = uy + (size_t)n * 65536;
    float uxx = gx_(uxp, h, w);
    float uyy = gy_(uyp, h, w);
    float uxy = gy_(uxp, h, w);
    float a = uxp[h * 256 + w], b = uyp[h * 256 + w];
    float den = 1.f + a * a + b * b;
    out[idx] = (uxx * uyy - uxy * uxy) / (den * den);
}

// ------------------------------ host side -----------------------------------
static inline int ceil_div(int a, int b) { return (a + b - 1) / b; }
static inline int smszA(int bn) { return (2 * 128 * 36 + 2 * bn * 36) * 4; }

static void run_stage(const float* dwW, const float* w1, const float* w2,
                      float* x, float* hbuf, float* ebuf, float* wdwT,
                      int C, int H, int W)
{
    int P = H * W, rows = NBATCH * P, tiles = rows / 128;
    int dwtot = 2 * 49 * C;
    dwT2_k<<<ceil_div(dwtot, 256), 256>>>(dwW, wdwT, C, dwtot);
    int dwthr = NBATCH * H * (W / 4) * (C / 4);
    for (int b = 0; b < 2; b++) {
        dw7_nhwc<<<ceil_div(dwthr, 256), 256>>>(x, wdwT + b * 49 * C, hbuf, C, H, W, dwthr);
        mma_gemm<128, 0><<<dim3(tiles, (4 * C) / 128), 256, smszA(128)>>>(
            hbuf, w1 + (size_t)b * 4 * C * C, ebuf, ebuf, C, 4 * C, 0, 0);
        const float* w2b = w2 + (size_t)b * C * 4 * C;
        if (C == 64)
            mma_gemm<64, 1><<<dim3(tiles, 1), 256, smszA(64)>>>(
                ebuf, w2b, x, x, 4 * C, C, 0, 0);
        else
            mma_gemm<128, 1><<<dim3(tiles, C / 128), 256, smszA(128)>>>(
                ebuf, w2b, x, x, 4 * C, C, 0, 0);
    }
}

static void run_down(const float* x, const float* wdn, float* hbuf, float* wd,
                     float* y, int Ci, int Co, int Ho, int Wo)
{
    int K = 4 * Ci;
    int wtot = Co * K;
    wdnR_k<<<ceil_div(wtot, 256), 256>>>(wdn, wd, Ci, wtot);
    int s2dtot = NBATCH * Ho * Wo * 4 * (Ci / 4);
    s2d_k<<<ceil_div(s2dtot, 256), 256>>>(x, hbuf, Ci, Ho, Wo, s2dtot);
    int tiles = NBATCH * Ho * Wo / 128;
    mma_gemm<128, 2><<<dim3(tiles, Co / 128), 256, smszA(128)>>>(
        hbuf, wd, y, y, K, Co, 0, 0);
}

static void run_up(const float* x, const float* wup, const float* skip, float* y,
                   float* wt, int Ci, int Co, int wsh)
{
    int M = Co * 4;
    int wtot = M * Ci;
    wupT_k<<<ceil_div(wtot, 256), 256>>>(wup, wt, Ci, M, wtot);
    int P_lo = 1 << (2 * wsh);
    int tiles = NBATCH * P_lo / 128;
    mma_gemm<128, 3><<<dim3(tiles, M / 128), 256, smszA(128)>>>(
        x, wt, y, skip, Ci, M, wsh, Co);
}

extern "C" void kernel_launch(void* const* d_in, const int* in_sizes, int n_in,
                              void* d_out, int out_size)
{
    const float* x0      = (const float*)d_in[0];
    const float* w_head  = (const float*)d_in[1];
    const float* en1_dw  = (const float*)d_in[2];
    const float* en1_w1  = (const float*)d_in[3];
    const float* en1_w2  = (const float*)d_in[4];
    const float* w_down1 = (const float*)d_in[5];
    const float* en2_dw  = (const float*)d_in[6];
    const float* en2_w1  = (const float*)d_in[7];
    const float* en2_w2  = (const float*)d_in[8];
    const float* w_down2 = (const float*)d_in[9];
    const float* en3_dw  = (const float*)d_in[10];
    const float* en3_w1  = (const float*)d_in[11];
    const float* en3_w2  = (const float*)d_in[12];
    const float* w_down3 = (const float*)d_in[13];
    const float* body_dw = (const float*)d_in[14];
    const float* body_w1 = (const float*)d_in[15];
    const float* body_w2 = (const float*)d_in[16];
    const float* w_up3   = (const float*)d_in[17];
    const float* de3_dw  = (const float*)d_in[18];
    const float* de3_w1  = (const float*)d_in[19];
    const float* de3_w2  = (const float*)d_in[20];
    const float* w_up2   = (const float*)d_in[21];
    const float* de2_dw  = (const float*)d_in[22];
    const float* de2_w1  = (const float*)d_in[23];
    const float* de2_w2  = (const float*)d_in[24];
    const float* w_up1   = (const float*)d_in[25];
    const float* de1_dw  = (const float*)d_in[26];
    const float* de1_w1  = (const float*)d_in[27];
    const float* de1_w2  = (const float*)d_in[28];
    const float* w_tail  = (const float*)d_in[29];
    float* out = (float*)d_out;

    cudaFuncSetAttribute(mma_gemm<128, 0>, cudaFuncAttributeMaxDynamicSharedMemorySize, smszA(128));
    cudaFuncSetAttribute(mma_gemm<128, 1>, cudaFuncAttributeMaxDynamicSharedMemorySize, smszA(128));
    cudaFuncSetAttribute(mma_gemm<64, 1>,  cudaFuncAttributeMaxDynamicSharedMemorySize, smszA(64));
    cudaFuncSetAttribute(mma_gemm<128, 2>, cudaFuncAttributeMaxDynamicSharedMemorySize, smszA(128));
    cudaFuncSetAttribute(mma_gemm<128, 3>, cudaFuncAttributeMaxDynamicSharedMemorySize, smszA(128));

    float *X1, *X2, *X3, *X4, *H, *E, *D3, *D2, *D1, *T, *U, *UX, *UY, *MN, *PS, *WT, *WD, *WDW, *WH, *WTL;
    cudaGetSymbolAddress((void**)&X1, g_x1);
    cudaGetSymbolAddress((void**)&X2, g_x2);
    cudaGetSymbolAddress((void**)&X3, g_x3);
    cudaGetSymbolAddress((void**)&X4, g_x4);
    cudaGetSymbolAddress((void**)&H,  g_h);
    cudaGetSymbolAddress((void**)&E,  g_e);
    cudaGetSymbolAddress((void**)&D3, g_d3);
    cudaGetSymbolAddress((void**)&D2, g_d2);
    cudaGetSymbolAddress((void**)&D1, g_d1);
    cudaGetSymbolAddress((void**)&T,  g_t);
    cudaGetSymbolAddress((void**)&U,  g_u);
    cudaGetSymbolAddress((void**)&UX, g_ux);
    cudaGetSymbolAddress((void**)&UY, g_uy);
    cudaGetSymbolAddress((void**)&MN, g_mn);
    cudaGetSymbolAddress((void**)&PS, g_ps);
    cudaGetSymbolAddress((void**)&WT, g_wt);
    cudaGetSymbolAddress((void**)&WD, g_wd);
    cudaGetSymbolAddress((void**)&WDW, g_wdw);
    cudaGetSymbolAddress((void**)&WH, g_wh);
    cudaGetSymbolAddress((void**)&WTL, g_wtl);

    // ---------------- encoder (NHWC) ----------------
    wheadT_k<<<3, 256>>>(w_head, WH);
    {
        int total = NBATCH * 65536 * 16;
        head_k<<<ceil_div(total, 256), 256>>>(x0, WH, X1, total);
    }
    run_stage(en1_dw, en1_w1, en1_w2, X1, H, E, WDW, 64, 256, 256);

    run_down(X1, w_down1, H, WD, X2, 64, 128, 128, 128);
    run_stage(en2_dw, en2_w1, en2_w2, X2, H, E, WDW, 128, 128, 128);

    run_down(X2, w_down2, H, WD, X3, 128, 256, 64, 64);
    run_stage(en3_dw, en3_w1, en3_w2, X3, H, E, WDW, 256, 64, 64);

    run_down(X3, w_down3, H, WD, X4, 256, 512, 32, 32);
    run_stage(body_dw, body_w1, body_w2, X4, H, E, WDW, 512, 32, 32);

    // ---------------- decoder ----------------
    run_up(X4, w_up3, X3, D3, WT, 512, 256, 5);
    run_stage(de3_dw, de3_w1, de3_w2, D3, H, E, WDW, 256, 64, 64);

    run_up(D3, w_up2, X2, D2, WT, 256, 128, 6);
    run_stage(de2_dw, de2_w1, de2_w2, D2, H, E, WDW, 128, 128, 128);

    run_up(D2, w_up1, X1, D1, WT, 128, 64, 7);
    run_stage(de1_dw, de1_w1, de1_w2, D1, H, E, WDW, 64, 256, 256);

    wtailT_k<<<5, 256>>>(w_tail, WTL);
    {
        int total = NBATCH * 65536;
        tail_k<<<ceil_div(total, 256), 256>>>(D1, WTL, T, total);
    }

    // ---------------- epilogue ----------------
    mean1_k<<<dim3(NBATCH, 32), 256>>>(T, PS);
    mean2_k<<<1, 32>>>(PS, MN);
    finalize1<<<2048, 256>>>(T, x0, MN, out, U);
    grad_k<<<2048, 256>>>(U, UX, UY);
    curv_k<<<2048, 256>>>(UX, UY, out + 1048576);
}

// round 11
// speedup vs baseline: 1.8192x; 1.1335x over previous
#include <cuda_runtime.h>
#include <cstdint>

#define NBATCH 8

// ------------------------- scratch (device globals) ------------------------
__device__ float g_x1[(size_t)NBATCH * 64 * 256 * 256];
__device__ float g_x2[(size_t)NBATCH * 128 * 128 * 128];
__device__ float g_x3[(size_t)NBATCH * 256 * 64 * 64];
__device__ float g_x4[(size_t)NBATCH * 512 * 32 * 32];
__device__ float g_h [(size_t)NBATCH * 64 * 256 * 256];   // dw / s2d scratch
__device__ float g_e [(size_t)NBATCH * 256 * 256 * 256];  // expand scratch
__device__ float g_d3[(size_t)NBATCH * 256 * 64 * 64];
__device__ float g_d2[(size_t)NBATCH * 128 * 128 * 128];
__device__ float g_d1[(size_t)NBATCH * 64 * 256 * 256];
__device__ float g_t [(size_t)NBATCH * 2 * 256 * 256];
__device__ float g_u [(size_t)NBATCH * 256 * 256];
__device__ float g_ux[(size_t)NBATCH * 256 * 256];
__device__ float g_uy[(size_t)NBATCH * 256 * 256];
__device__ float g_mn[NBATCH];
__device__ float g_ps[NBATCH * 32];    // mean partials
__device__ float g_wt[1024 * 512];     // up-weight transpose
__device__ float g_wd[512 * 1024];     // down-weight reorder
__device__ float g_wdw[2 * 49 * 512];  // dw-weight transpose
__device__ float g_wh[9 * 64];         // head weight transpose
__device__ float g_wtl[2 * 9 * 64];    // tail weight transpose

// ----------------------------- PTX helpers ---------------------------------
__device__ __forceinline__ uint32_t smem_u32(const void* p) {
    uint32_t a;
    asm("{ .reg .u64 t; cvta.to.shared.u64 t, %1; cvt.u32.u64 %0, t; }" : "=r"(a) : "l"(p));
    return a;
}
__device__ __forceinline__ void cp16(uint32_t dst, const void* src) {
    asm volatile("cp.async.cg.shared.global [%0], [%1], 16;" :: "r"(dst), "l"(src));
}
__device__ __forceinline__ void cp_commit() {
    asm volatile("cp.async.commit_group;" ::: "memory");
}
template <int N>
__device__ __forceinline__ void cp_wait() {
    asm volatile("cp.async.wait_group %0;" :: "n"(N) : "memory");
}
__device__ __forceinline__ void mma8(float* c, const uint32_t* a, const uint32_t* b) {
    asm volatile(
        "mma.sync.aligned.m16n8k8.row.col.f32.tf32.tf32.f32 "
        "{%0,%1,%2,%3}, {%4,%5,%6,%7}, {%8,%9}, {%0,%1,%2,%3};"
        : "+f"(c[0]), "+f"(c[1]), "+f"(c[2]), "+f"(c[3])
        : "r"(a[0]), "r"(a[1]), "r"(a[2]), "r"(a[3]), "r"(b[0]), "r"(b[1]));
}
// split x into hi (tf32, round-to-nearest) and lo (residual, raw fp32 bits)
__device__ __forceinline__ void tf32_split(float v, uint32_t& hi, uint32_t& lo) {
    asm("cvt.rna.tf32.f32 %0, %1;" : "=r"(hi) : "f"(v));
    lo = __float_as_uint(v - __uint_as_float(hi));
}

// ------------------------------ 3xTF32 MMA GEMM -----------------------------
// C[row,n] = epi( sum_k A[row,k]*B[n,k] ); rows = NHWC pixels (NBATCH*H*W).
// Tile: 128 x BN x 32, 8 warps. EPI: 0 relu, 1 +Base, 2 plain,
// 3 pixel-shuffle up-scatter + skip add (Base=skip; wsh=log2(W_lo); Cout).
template <int BN, int EPI>
__global__ __launch_bounds__(256, 2) void mma_gemm(
    const float* __restrict__ A, const float* __restrict__ B,
    float* __restrict__ Cp, const float* __restrict__ Base,
    int K, int Ntot, int wsh, int Cout)
{
    extern __shared__ float sm[];
    float* As = sm;                    // [2][128][36]
    float* Bs = sm + 2 * 128 * 36;     // [2][BN][36]
    const uint32_t sbase = smem_u32(sm);
    constexpr uint32_t BOFF = 2u * 128u * 36u * 4u;

    const int tid = threadIdx.x, wid = tid >> 5, lid = tid & 31;
    const int g = lid >> 2, tig = lid & 3;
    constexpr int MF = (BN == 128) ? 4 : 2;
    const int m0w = (BN == 128) ? (wid >> 2) * 64 : (wid >> 1) * 32;
    const int n0w = (BN == 128) ? (wid & 3) * 32 : (wid & 1) * 32;
    const int m0 = blockIdx.x * 128, n0 = blockIdx.y * BN;

    const float* Ag = A + (size_t)m0 * K;
    const float* Bg = B + (size_t)n0 * K;

    float acc[MF][4][4];
#pragma unroll
    for (int i = 0; i < MF; i++)
#pragma unroll
        for (int j = 0; j < 4; j++)
#pragma unroll
            for (int e = 0; e < 4; e++) acc[i][j][e] = 0.f;

    const int nc = K >> 5;

    // prefetch chunk 0 into buf 0
    {
#pragma unroll
        for (int i = 0; i < 4; i++) {
            int idx = tid + i * 256, r = idx >> 3, q = idx & 7;
            cp16(sbase + (uint32_t)(r * 36 + q * 4) * 4, Ag + (size_t)r * K + q * 4);
        }
#pragma unroll
        for (int i = 0; i < BN / 32; i++) {
            int idx = tid + i * 256, r = idx >> 3, q = idx & 7;
            cp16(sbase + BOFF + (uint32_t)(r * 36 + q * 4) * 4, Bg + (size_t)r * K + q * 4);
        }
        cp_commit();
    }

    for (int ck = 0; ck < nc; ck++) {
        const int buf = ck & 1;
        if (ck + 1 < nc) {
            const int nb = buf ^ 1;
            const float* Ab = Ag + (ck + 1) * 32;
#pragma unroll
            for (int i = 0; i < 4; i++) {
                int idx = tid + i * 256, r = idx >> 3, q = idx & 7;
                cp16(sbase + (uint32_t)(nb * 128 * 36 + r * 36 + q * 4) * 4,
                     Ab + (size_t)r * K + q * 4);
            }
            const float* Bb = Bg + (ck + 1) * 32;
#pragma unroll
            for (int i = 0; i < BN / 32; i++) {
                int idx = tid + i * 256, r = idx >> 3, q = idx & 7;
                cp16(sbase + BOFF + (uint32_t)(nb * BN * 36 + r * 36 + q * 4) * 4,
                     Bb + (size_t)r * K + q * 4);
            }
            cp_commit();
            cp_wait<1>();
        } else {
            cp_wait<0>();
        }
        __syncthreads();

        const float* Ab = As + buf * 128 * 36;
        const float* Bb = Bs + buf * BN * 36;
#pragma unroll
        for (int s = 0; s < 4; s++) {
            const int k = s * 8;
            uint32_t ah[MF][4], al[MF][4], bh[4][2], bl[4][2];
#pragma unroll
            for (int mf = 0; mf < MF; mf++) {
                const float* ap = Ab + (m0w + mf * 16 + g) * 36 + k + tig;
                tf32_split(ap[0],          ah[mf][0], al[mf][0]);
                tf32_split(ap[8 * 36],     ah[mf][1], al[mf][1]);
                tf32_split(ap[4],          ah[mf][2], al[mf][2]);
                tf32_split(ap[8 * 36 + 4], ah[mf][3], al[mf][3]);
            }
#pragma unroll
            for (int nf = 0; nf < 4; nf++) {
                const float* bp = Bb + (n0w + nf * 8 + g) * 36 + k + tig;
                tf32_split(bp[0], bh[nf][0], bl[nf][0]);
                tf32_split(bp[4], bh[nf][1], bl[nf][1]);
            }
            // 3xTF32: hi*hi + hi*lo + lo*hi (lo*lo dropped, ~2^-22)
#pragma unroll
            for (int mf = 0; mf < MF; mf++)
#pragma unroll
                for (int nf = 0; nf < 4; nf++) {
                    mma8(acc[mf][nf], al[mf], bh[nf]);
                    mma8(acc[mf][nf], ah[mf], bl[nf]);
                    mma8(acc[mf][nf], ah[mf], bh[nf]);
                }
        }
        __syncthreads();
    }

    // ------------------------------ epilogue --------------------------------
#pragma unroll
    for (int mf = 0; mf < MF; mf++) {
        const int r0 = m0 + m0w + mf * 16 + g;
        const int r1 = r0 + 8;
#pragma unroll
        for (int nf = 0; nf < 4; nf++) {
            const int col = n0 + n0w + nf * 8 + tig * 2;
            if (EPI == 3) {
#pragma unroll
                for (int half = 0; half < 2; half++) {
                    const int row = half ? r1 : r0;
                    const int n = row >> (2 * wsh);
                    const int rem = row & ((1 << (2 * wsh)) - 1);
                    const int h = rem >> wsh, w = rem & ((1 << wsh) - 1);
#pragma unroll
                    for (int e = 0; e < 2; e++) {
                        const int c = col + e;
                        const int o = c >> 2, a = (c >> 1) & 1, b = c & 1;
                        size_t pix = ((size_t)n << (2 * wsh + 2))
                                   + (size_t)((2 * h + a) << (wsh + 1)) + 2 * w + b;
                        size_t adr = pix * Cout + o;
                        Cp[adr] = acc[mf][nf][half * 2 + e] + Base[adr];
                    }
                }
            } else {
                size_t off0 = (size_t)r0 * Ntot + col;
                size_t off1 = (size_t)r1 * Ntot + col;
                float2 v0 = make_float2(acc[mf][nf][0], acc[mf][nf][1]);
                float2 v1 = make_float2(acc[mf][nf][2], acc[mf][nf][3]);
                if (EPI == 0) {
                    v0.x = fmaxf(v0.x, 0.f); v0.y = fmaxf(v0.y, 0.f);
                    v1.x = fmaxf(v1.x, 0.f); v1.y = fmaxf(v1.y, 0.f);
                } else if (EPI == 1) {
                    float2 b0 = *(const float2*)(Base + off0);
                    float2 b1 = *(const float2*)(Base + off1);
                    v0.x += b0.x; v0.y += b0.y;
                    v1.x += b1.x; v1.y += b1.y;
                }
                *(float2*)(Cp + off0) = v0;
                *(float2*)(Cp + off1) = v1;
            }
        }
    }
}

// ------------------------- depthwise 7x7 (NHWC) -----------------------------
__device__ __forceinline__ void f4fma(float4& a, float4 w, float4 x) {
    a.x += w.x * x.x; a.y += w.y * x.y; a.z += w.z * x.z; a.w += w.w * x.w;
}
__global__ __launch_bounds__(256) void dw7_nhwc(
    const float* __restrict__ x, const float* __restrict__ wT,
    float* __restrict__ y, int C, int H, int W, int total)
{
    int idx = blockIdx.x * blockDim.x + threadIdx.x;
    if (idx >= total) return;
    const int C4 = C >> 2;
    int c4 = idx % C4;
    int t = idx / C4;
    int w4 = t % (W >> 2); t /= (W >> 2);
    int h = t % H;
    int n = t / H;
    int w0 = w4 * 4;
    const float* xb = x + (size_t)n * H * W * C + (size_t)c4 * 4;
    float4 acc[4];
#pragma unroll
    for (int j = 0; j < 4; j++) acc[j] = make_float4(0.f, 0.f, 0.f, 0.f);

    const bool interior = (h >= 3) & (h < H - 3) & (w0 >= 4) & (w0 <= W - 8);
    if (interior) {
        // branch-free fully unrolled body
        const float* xc = xb + ((size_t)(h - 3) * W + (w0 - 3)) * C;
#pragma unroll
        for (int dy = 0; dy < 7; dy++) {
            const float* xrow = xc + (size_t)dy * W * C;
            float4 wv[7];
#pragma unroll
            for (int k = 0; k < 7; k++)
                wv[k] = *(const float4*)(wT + (size_t)(dy * 7 + k) * C + c4 * 4);
#pragma unroll
            for (int dx = 0; dx < 10; dx++) {
                float4 xv = *(const float4*)(xrow + (size_t)dx * C);
#pragma unroll
                for (int j = 0; j < 4; j++) {
                    int k = dx - j;
                    if (k >= 0 && k < 7) f4fma(acc[j], wv[k], xv);
                }
            }
        }
    } else {
        for (int dy = 0; dy < 7; dy++) {
            int hy = h + dy - 3;
            if ((unsigned)hy >= (unsigned)H) continue;
            const float* xrow = xb + (size_t)hy * W * C;
            float4 wv[7];
#pragma unroll
            for (int k = 0; k < 7; k++)
                wv[k] = *(const float4*)(wT + (size_t)(dy * 7 + k) * C + c4 * 4);
#pragma unroll
            for (int dx = 0; dx < 10; dx++) {
                int wx = w0 + dx - 3;
                if ((unsigned)wx >= (unsigned)W) continue;
                float4 xv = *(const float4*)(xb + ((size_t)hy * W + wx) * C - (size_t)hy * W * C + (size_t)wx * C);
                // (simplify: xv from xrow)
                xv = *(const float4*)(xrow + (size_t)wx * C);
#pragma unroll
                for (int j = 0; j < 4; j++) {
                    int k = dx - j;
                    if (k >= 0 && k < 7) f4fma(acc[j], wv[k], xv);
                }
            }
        }
    }
    float* yb = y + ((size_t)(n * H + h) * W + w0) * C + c4 * 4;
#pragma unroll
    for (int j = 0; j < 4; j++) *(float4*)(yb + (size_t)j * C) = acc[j];
}

// --------------------------- weight prep ------------------------------------
__global__ void dwT2_k(const float* __restrict__ dw, float* __restrict__ o,
                       int C, int total) {
    int idx = blockIdx.x * blockDim.x + threadIdx.x;
    if (idx >= total) return;
    int b = idx / (49 * C), r = idx % (49 * C);
    int tap = r / C, c = r % C;
    o[idx] = dw[(size_t)b * C * 49 + c * 49 + tap];
}
__global__ void wheadT_k(const float* __restrict__ w, float* __restrict__ o) {
    int idx = blockIdx.x * blockDim.x + threadIdx.x;
    if (idx >= 576) return;
    int tap = idx / 64, oc = idx % 64;
    o[idx] = w[oc * 9 + tap];
}
__global__ void wtailT_k(const float* __restrict__ w, float* __restrict__ o) {
    int idx = blockIdx.x * blockDim.x + threadIdx.x;
    if (idx >= 1152) return;
    int oc = idx / 576, r = idx % 576;
    int tap = r / 64, c = r % 64;
    o[oc * 576 + tap * 64 + c] = w[(oc * 64 + c) * 9 + tap];
}
__global__ void wdnR_k(const float* __restrict__ w, float* __restrict__ o,
                       int Ci, int total) {
    int idx = blockIdx.x * blockDim.x + threadIdx.x;
    if (idx >= total) return;
    int K4 = 4 * Ci;
    int co = idx / K4, k = idx % K4;
    int ab = k / Ci, ci = k % Ci;
    o[idx] = w[(size_t)co * K4 + ci * 4 + ab];
}
__global__ void wupT_k(const float* __restrict__ w, float* __restrict__ o,
                       int Ci, int M, int total) {
    int idx = blockIdx.x * blockDim.x + threadIdx.x;
    if (idx >= total) return;
    int ci = idx % Ci, m = idx / Ci;
    o[idx] = w[(size_t)ci * M + m];
}

// ----------------------- space-to-depth (NHWC, ab-major K) ------------------
__global__ void s2d_k(const float* __restrict__ x, float* __restrict__ o,
                      int Ci, int Ho, int Wo, int total)
{
    int idx = blockIdx.x * blockDim.x + threadIdx.x;
    if (idx >= total) return;
    const int Ci4 = Ci >> 2;
    int ci4 = idx % Ci4;
    int t = idx / Ci4;
    int ab = t & 3; t >>= 2;
    int wo = t % Wo; t /= Wo;
    int ho = t % Ho;
    int n = t / Ho;
    int a = ab >> 1, bq = ab & 1;
    int Wi = 2 * Wo;
    float4 v = *(const float4*)(x
        + ((size_t)(n * 2 * Ho + 2 * ho + a) * Wi + 2 * wo + bq) * Ci + ci4 * 4);
    *(float4*)(o + ((size_t)((n * Ho + ho) * Wo + wo)) * 4 * Ci
               + (size_t)ab * Ci + ci4 * 4) = v;
}

// ------------------------------ head / tail ---------------------------------
__global__ void head_k(const float* __restrict__ x0, const float* __restrict__ wT,
                       float* __restrict__ y, int total)
{
    int idx = blockIdx.x * blockDim.x + threadIdx.x;
    if (idx >= total) return;
    int o4 = idx & 15;
    int p = idx >> 4;
    int hw = p & 65535, n = p >> 16;
    int h = hw >> 8, w = hw & 255;
    const float* xp = x0 + (size_t)n * 65536;
    float4 acc = make_float4(0.f, 0.f, 0.f, 0.f);
#pragma unroll
    for (int dy = 0; dy < 3; dy++) {
        int yy = h + dy - 1;
        if ((unsigned)yy >= 256u) continue;
#pragma unroll
        for (int dx = 0; dx < 3; dx++) {
            int xx = w + dx - 1;
            if ((unsigned)xx >= 256u) continue;
            float xv = xp[yy * 256 + xx];
            float4 wv = *(const float4*)(wT + (dy * 3 + dx) * 64 + o4 * 4);
            acc.x += xv * wv.x; acc.y += xv * wv.y;
            acc.z += xv * wv.z; acc.w += xv * wv.w;
        }
    }
    *(float4*)(y + (size_t)p * 64 + o4 * 4) = acc;
}

__global__ void tail_k(const float* __restrict__ x, const float* __restrict__ wt,
                       float* __restrict__ T, int total)
{
    int idx = blockIdx.x * blockDim.x + threadIdx.x;
    if (idx >= total) return;
    int n = idx >> 16, hw = idx & 65535;
    int h = hw >> 8, w = hw & 255;
    const float* xn = x + (size_t)n * 65536 * 64;
    float a0 = 0.f, a1 = 0.f;
    for (int dy = 0; dy < 3; dy++) {
        int yy = h + dy - 1;
        if ((unsigned)yy >= 256u) continue;
        for (int dx = 0; dx < 3; dx++) {
            int xx = w + dx - 1;
            if ((unsigned)xx >= 256u) continue;
            int tap = dy * 3 + dx;
            const float* xp = xn + ((size_t)yy * 256 + xx) * 64;
            const float* w0p = wt + tap * 64;
            const float* w1p = wt + 576 + tap * 64;
#pragma unroll
            for (int c4 = 0; c4 < 16; c4++) {
                float4 xv = *(const float4*)(xp + c4 * 4);
                float4 w0 = *(const float4*)(w0p + c4 * 4);
                float4 w1 = *(const float4*)(w1p + c4 * 4);
                a0 += xv.x * w0.x + xv.y * w0.y + xv.z * w0.z + xv.w * w0.w;
                a1 += xv.x * w1.x + xv.y * w1.y + xv.z * w1.z + xv.w * w1.w;
            }
        }
    }
    T[(size_t)n * 131072 + hw] = a0;
    T[(size_t)n * 131072 + 65536 + hw] = a1;
}

// ------------------------------ epilogue ------------------------------------
__global__ void mean1_k(const float* __restrict__ tail, float* __restrict__ ps)
{
    __shared__ float s[256];
    int n = blockIdx.x, j = blockIdx.y;
    const float* p = tail + (size_t)n * 131072 + j * 2048;
    float acc = 0.f;
    for (int i = threadIdx.x; i < 2048; i += 256) acc += p[i];
    s[threadIdx.x] = acc;
    __syncthreads();
    for (int st = 128; st > 0; st >>= 1) {
        if (threadIdx.x < st) s[threadIdx.x] += s[threadIdx.x + st];
        __syncthreads();
    }
    if (threadIdx.x == 0) ps[n * 32 + j] = s[0];
}
__global__ void mean2_k(const float* __restrict__ ps, float* __restrict__ mean)
{
    int t = threadIdx.x;
    if (t < NBATCH) {
        float s = 0.f;
        for (int j = 0; j < 32; j++) s += ps[t * 32 + j];
        mean[t] = s * (1.f / 65536.f);
    }
}

__global__ void finalize1(const float* __restrict__ tail, const float* __restrict__ x0,
                          const float* __restrict__ mean, float* __restrict__ out,
                          float* __restrict__ u)
{
    int idx = blockIdx.x * blockDim.x + threadIdx.x;
    if (idx >= 524288) return;
    int n = idx >> 16, p = idx & 65535;
    float nd = tail[(size_t)n * 131072 + 65536 + p];
    out[idx] = mean[n];
    out[524288 + idx] = nd;
    u[idx] = nd + x0[idx];
}

__device__ __forceinline__ float gx_(const float* u, int h, int w) {
    if (w == 0)   return u[h * 256 + 1] - u[h * 256];
    if (w == 255) return u[h * 256 + 255] - u[h * 256 + 254];
    return 0.5f * (u[h * 256 + w + 1] - u[h * 256 + w - 1]);
}
__device__ __forceinline__ float gy_(const float* u, int h, int w) {
    if (h == 0)   return u[256 + w] - u[w];
    if (h == 255) return u[255 * 256 + w] - u[254 * 256 + w];
    return 0.5f * (u[(h + 1) * 256 + w] - u[(h - 1) * 256 + w]);
}

__global__ void grad_k(const float* __restrict__ u, float* __restrict__ ux,
                       float* __restrict__ uy)
{
    int idx = blockIdx.x * blockDim.x + threadIdx.x;
    if (idx >= 524288) return;
    int n = idx >> 16, p = idx & 65535;
    int h = p >> 8, w = p & 255;
    const float* up = u + (size_t)n * 65536;
    ux[idx] = gx_(up, h, w);
    uy[idx] = gy_(up, h, w);
}

__global__ void curv_k(const float* __restrict__ ux, const float* __restrict__ uy,
                       float* __restrict__ out)
{
    int idx = blockIdx.x * blockDim.x + threadIdx.x;
    if (idx >= 524288) return;
    int n = idx >> 16, p = idx & 65535;
    int h = p >> 8, w = p & 255;
    const float* uxp = ux + (size_t)n * 65536;
    const float* uyp = uy + (size_t)n * 65536;
    float uxx = gx_(uxp, h, w);
    float uyy = gy_(uyp, h, w);
    float uxy = gy_(uxp, h, w);
    float a = uxp[h * 256 + w], b = uyp[h * 256 + w];
    float den = 1.f + a * a + b * b;
    out[idx] = (uxx * uyy - uxy * uxy) / (den * den);
}

// ------------------------------ host side -----------------------------------
static inline int ceil_div(int a, int b) { return (a + b - 1) / b; }
static inline int smszA(int bn) { return (2 * 128 * 36 + 2 * bn * 36) * 4; }

static void run_stage(const float* dwW, const float* w1, const float* w2,
                      float* x, float* hbuf, float* ebuf, float* wdwT,
                      int C, int H, int W)
{
    int P = H * W, rows = NBATCH * P, tiles = rows / 128;
    int dwtot = 2 * 49 * C;
    dwT2_k<<<ceil_div(dwtot, 256), 256>>>(dwW, wdwT, C, dwtot);
    int dwthr = NBATCH * H * (W / 4) * (C / 4);
    for (int b = 0; b < 2; b++) {
        dw7_nhwc<<<ceil_div(dwthr, 256), 256>>>(x, wdwT + b * 49 * C, hbuf, C, H, W, dwthr);
        mma_gemm<128, 0><<<dim3(tiles, (4 * C) / 128), 256, smszA(128)>>>(
            hbuf, w1 + (size_t)b * 4 * C * C, ebuf, ebuf, C, 4 * C, 0, 0);
        const float* w2b = w2 + (size_t)b * C * 4 * C;
        if (C == 64)
            mma_gemm<64, 1><<<dim3(tiles, 1), 256, smszA(64)>>>(
                ebuf, w2b, x, x, 4 * C, C, 0, 0);
        else
            mma_gemm<128, 1><<<dim3(tiles, C / 128), 256, smszA(128)>>>(
                ebuf, w2b, x, x, 4 * C, C, 0, 0);
    }
}

static void run_down(const float* x, const float* wdn, float* hbuf, float* wd,
                     float* y, int Ci, int Co, int Ho, int Wo)
{
    int K = 4 * Ci;
    int wtot = Co * K;
    wdnR_k<<<ceil_div(wtot, 256), 256>>>(wdn, wd, Ci, wtot);
    int s2dtot = NBATCH * Ho * Wo * 4 * (Ci / 4);
    s2d_k<<<ceil_div(s2dtot, 256), 256>>>(x, hbuf, Ci, Ho, Wo, s2dtot);
    int tiles = NBATCH * Ho * Wo / 128;
    mma_gemm<128, 2><<<dim3(tiles, Co / 128), 256, smszA(128)>>>(
        hbuf, wd, y, y, K, Co, 0, 0);
}

static void run_up(const float* x, const float* wup, const float* skip, float* y,
                   float* wt, int Ci, int Co, int wsh)
{
    int M = Co * 4;
    int wtot = M * Ci;
    wupT_k<<<ceil_div(wtot, 256), 256>>>(wup, wt, Ci, M, wtot);
    int P_lo = 1 << (2 * wsh);
    int tiles = NBATCH * P_lo / 128;
    mma_gemm<128, 3><<<dim3(tiles, M / 128), 256, smszA(128)>>>(
        x, wt, y, skip, Ci, M, wsh, Co);
}

extern "C" void kernel_launch(void* const* d_in, const int* in_sizes, int n_in,
                              void* d_out, int out_size)
{
    const float* x0      = (const float*)d_in[0];
    const float* w_head  = (const float*)d_in[1];
    const float* en1_dw  = (const float*)d_in[2];
    const float* en1_w1  = (const float*)d_in[3];
    const float* en1_w2  = (const float*)d_in[4];
    const float* w_down1 = (const float*)d_in[5];
    const float* en2_dw  = (const float*)d_in[6];
    const float* en2_w1  = (const float*)d_in[7];
    const float* en2_w2  = (const float*)d_in[8];
    const float* w_down2 = (const float*)d_in[9];
    const float* en3_dw  = (const float*)d_in[10];
    const float* en3_w1  = (const float*)d_in[11];
    const float* en3_w2  = (const float*)d_in[12];
    const float* w_down3 = (const float*)d_in[13];
    const float* body_dw = (const float*)d_in[14];
    const float* body_w1 = (const float*)d_in[15];
    const float* body_w2 = (const float*)d_in[16];
    const float* w_up3   = (const float*)d_in[17];
    const float* de3_dw  = (const float*)d_in[18];
    const float* de3_w1  = (const float*)d_in[19];
    const float* de3_w2  = (const float*)d_in[20];
    const float* w_up2   = (const float*)d_in[21];
    const float* de2_dw  = (const float*)d_in[22];
    const float* de2_w1  = (const float*)d_in[23];
    const float* de2_w2  = (const float*)d_in[24];
    const float* w_up1   = (const float*)d_in[25];
    const float* de1_dw  = (const float*)d_in[26];
    const float* de1_w1  = (const float*)d_in[27];
    const float* de1_w2  = (const float*)d_in[28];
    const float* w_tail  = (const float*)d_in[29];
    float* out = (float*)d_out;

    cudaFuncSetAttribute(mma_gemm<128, 0>, cudaFuncAttributeMaxDynamicSharedMemorySize, smszA(128));
    cudaFuncSetAttribute(mma_gemm<128, 1>, cudaFuncAttributeMaxDynamicSharedMemorySize, smszA(128));
    cudaFuncSetAttribute(mma_gemm<64, 1>,  cudaFuncAttributeMaxDynamicSharedMemorySize, smszA(64));
    cudaFuncSetAttribute(mma_gemm<128, 2>, cudaFuncAttributeMaxDynamicSharedMemorySize, smszA(128));
    cudaFuncSetAttribute(mma_gemm<128, 3>, cudaFuncAttributeMaxDynamicSharedMemorySize, smszA(128));

    float *X1, *X2, *X3, *X4, *H, *E, *D3, *D2, *D1, *T, *U, *UX, *UY, *MN, *PS, *WT, *WD, *WDW, *WH, *WTL;
    cudaGetSymbolAddress((void**)&X1, g_x1);
    cudaGetSymbolAddress((void**)&X2, g_x2);
    cudaGetSymbolAddress((void**)&X3, g_x3);
    cudaGetSymbolAddress((void**)&X4, g_x4);
    cudaGetSymbolAddress((void**)&H,  g_h);
    cudaGetSymbolAddress((void**)&E,  g_e);
    cudaGetSymbolAddress((void**)&D3, g_d3);
    cudaGetSymbolAddress((void**)&D2, g_d2);
    cudaGetSymbolAddress((void**)&D1, g_d1);
    cudaGetSymbolAddress((void**)&T,  g_t);
    cudaGetSymbolAddress((void**)&U,  g_u);
    cudaGetSymbolAddress((void**)&UX, g_ux);
    cudaGetSymbolAddress((void**)&UY, g_uy);
    cudaGetSymbolAddress((void**)&MN, g_mn);
    cudaGetSymbolAddress((void**)&PS, g_ps);
    cudaGetSymbolAddress((void**)&WT, g_wt);
    cudaGetSymbolAddress((void**)&WD, g_wd);
    cudaGetSymbolAddress((void**)&WDW, g_wdw);
    cudaGetSymbolAddress((void**)&WH, g_wh);
    cudaGetSymbolAddress((void**)&WTL, g_wtl);

    // ---------------- encoder (NHWC) ----------------
    wheadT_k<<<3, 256>>>(w_head, WH);
    {
        int total = NBATCH * 65536 * 16;
        head_k<<<ceil_div(total, 256), 256>>>(x0, WH, X1, total);
    }
    run_stage(en1_dw, en1_w1, en1_w2, X1, H, E, WDW, 64, 256, 256);

    run_down(X1, w_down1, H, WD, X2, 64, 128, 128, 128);
    run_stage(en2_dw, en2_w1, en2_w2, X2, H, E, WDW, 128, 128, 128);

    run_down(X2, w_down2, H, WD, X3, 128, 256, 64, 64);
    run_stage(en3_dw, en3_w1, en3_w2, X3, H, E, WDW, 256, 64, 64);

    run_down(X3, w_down3, H, WD, X4, 256, 512, 32, 32);
    run_stage(body_dw, body_w1, body_w2, X4, H, E, WDW, 512, 32, 32);

    // ---------------- decoder ----------------
    run_up(X4, w_up3, X3, D3, WT, 512, 256, 5);
    run_stage(de3_dw, de3_w1, de3_w2, D3, H, E, WDW, 256, 64, 64);

    run_up(D3, w_up2, X2, D2, WT, 256, 128, 6);
    run_stage(de2_dw, de2_w1, de2_w2, D2, H, E, WDW, 128, 128, 128);

    run_up(D2, w_up1, X1, D1, WT, 128, 64, 7);
    run_stage(de1_dw, de1_w1, de1_w2, D1, H, E, WDW, 64, 256, 256);

    wtailT_k<<<5, 256>>>(w_tail, WTL);
    {
        int total = NBATCH * 65536;
        tail_k<<<ceil_div(total, 256), 256>>>(D1, WTL, T, total);
    }

    // ---------------- epilogue ----------------
    mean1_k<<<dim3(NBATCH, 32), 256>>>(T, PS);
    mean2_k<<<1, 32>>>(PS, MN);
    finalize1<<<2048, 256>>>(T, x0, MN, out, U);
    grad_k<<<2048, 256>>>(U, UX, UY);
    curv_k<<<2048, 256>>>(UX, UY, out + 1048576);
}

// round 12
// speedup vs baseline: 1.8192x; 1.0000x over previous
#include <cuda_runtime.h>
#include <cstdint>

#define NBATCH 8

// ------------------------- scratch (device globals) ------------------------
__device__ float g_x1[(size_t)NBATCH * 64 * 256 * 256];
__device__ float g_x2[(size_t)NBATCH * 128 * 128 * 128];
__device__ float g_x3[(size_t)NBATCH * 256 * 64 * 64];
__device__ float g_x4[(size_t)NBATCH * 512 * 32 * 32];
__device__ float g_h [(size_t)NBATCH * 64 * 256 * 256];   // dw / s2d scratch
__device__ float g_e [(size_t)NBATCH * 256 * 256 * 256];  // expand scratch
__device__ float g_d3[(size_t)NBATCH * 256 * 64 * 64];
__device__ float g_d2[(size_t)NBATCH * 128 * 128 * 128];
__device__ float g_d1[(size_t)NBATCH * 64 * 256 * 256];
__device__ float g_t [(size_t)NBATCH * 2 * 256 * 256];
__device__ float g_u [(size_t)NBATCH * 256 * 256];
__device__ float g_ux[(size_t)NBATCH * 256 * 256];
__device__ float g_uy[(size_t)NBATCH * 256 * 256];
__device__ float g_mn[NBATCH];
__device__ float g_ps[NBATCH * 32];    // mean partials
__device__ float g_wt[1024 * 512];     // up-weight transpose
__device__ float g_wd[512 * 1024];     // down-weight reorder
__device__ float g_wdw[2 * 49 * 512];  // dw-weight transpose
__device__ float g_wh[9 * 64];         // head weight transpose
__device__ float g_wtl[2 * 9 * 64];    // tail weight transpose

// ----------------------------- PTX helpers ---------------------------------
__device__ __forceinline__ uint32_t smem_u32(const void* p) {
    uint32_t a;
    asm("{ .reg .u64 t; cvta.to.shared.u64 t, %1; cvt.u32.u64 %0, t; }" : "=r"(a) : "l"(p));
    return a;
}
__device__ __forceinline__ void cp16(uint32_t dst, const void* src) {
    asm volatile("cp.async.cg.shared.global [%0], [%1], 16;" :: "r"(dst), "l"(src));
}
__device__ __forceinline__ void cp_commit() {
    asm volatile("cp.async.commit_group;" ::: "memory");
}
template <int N>
__device__ __forceinline__ void cp_wait() {
    asm volatile("cp.async.wait_group %0;" :: "n"(N) : "memory");
}
__device__ __forceinline__ void mma8(float* c, const uint32_t* a, const uint32_t* b) {
    asm volatile(
        "mma.sync.aligned.m16n8k8.row.col.f32.tf32.tf32.f32 "
        "{%0,%1,%2,%3}, {%4,%5,%6,%7}, {%8,%9}, {%0,%1,%2,%3};"
        : "+f"(c[0]), "+f"(c[1]), "+f"(c[2]), "+f"(c[3])
        : "r"(a[0]), "r"(a[1]), "r"(a[2]), "r"(a[3]), "r"(b[0]), "r"(b[1]));
}
// split x into hi (tf32, round-to-nearest) and lo (residual, raw fp32 bits)
__device__ __forceinline__ void tf32_split(float v, uint32_t& hi, uint32_t& lo) {
    asm("cvt.rna.tf32.f32 %0, %1;" : "=r"(hi) : "f"(v));
    lo = __float_as_uint(v - __uint_as_float(hi));
}

// ------------------------------ 3xTF32 MMA GEMM -----------------------------
// C[row,n] = epi( sum_k A[row,k]*B[n,k] ); rows = NHWC pixels (NBATCH*H*W).
// Tile: 128 x BN x 32, 8 warps. Grid: (n_tiles, m_tiles) — n fastest so
// co-resident CTAs share the A row-tile (L2 dedup of A traffic).
// EPI: 0 relu, 1 +Base, 2 plain, 3 pixel-shuffle up-scatter + skip add.
template <int BN, int EPI>
__global__ __launch_bounds__(256, 2) void mma_gemm(
    const float* __restrict__ A, const float* __restrict__ B,
    float* __restrict__ Cp, const float* __restrict__ Base,
    int K, int Ntot, int wsh, int Cout)
{
    extern __shared__ float sm[];
    float* As = sm;                    // [2][128][36]
    float* Bs = sm + 2 * 128 * 36;     // [2][BN][36]
    const uint32_t sbase = smem_u32(sm);
    constexpr uint32_t BOFF = 2u * 128u * 36u * 4u;

    const int tid = threadIdx.x, wid = tid >> 5, lid = tid & 31;
    const int g = lid >> 2, tig = lid & 3;
    constexpr int MF = (BN == 128) ? 4 : 2;
    const int m0w = (BN == 128) ? (wid >> 2) * 64 : (wid >> 1) * 32;
    const int n0w = (BN == 128) ? (wid & 3) * 32 : (wid & 1) * 32;
    const int m0 = blockIdx.y * 128, n0 = blockIdx.x * BN;

    const float* Ag = A + (size_t)m0 * K;
    const float* Bg = B + (size_t)n0 * K;

    float acc[MF][4][4];
#pragma unroll
    for (int i = 0; i < MF; i++)
#pragma unroll
        for (int j = 0; j < 4; j++)
#pragma unroll
            for (int e = 0; e < 4; e++) acc[i][j][e] = 0.f;

    const int nc = K >> 5;

    // prefetch chunk 0 into buf 0
    {
#pragma unroll
        for (int i = 0; i < 4; i++) {
            int idx = tid + i * 256, r = idx >> 3, q = idx & 7;
            cp16(sbase + (uint32_t)(r * 36 + q * 4) * 4, Ag + (size_t)r * K + q * 4);
        }
#pragma unroll
        for (int i = 0; i < BN / 32; i++) {
            int idx = tid + i * 256, r = idx >> 3, q = idx & 7;
            cp16(sbase + BOFF + (uint32_t)(r * 36 + q * 4) * 4, Bg + (size_t)r * K + q * 4);
        }
        cp_commit();
    }

    for (int ck = 0; ck < nc; ck++) {
        const int buf = ck & 1;
        if (ck + 1 < nc) {
            const int nb = buf ^ 1;
            const float* Ab = Ag + (ck + 1) * 32;
#pragma unroll
            for (int i = 0; i < 4; i++) {
                int idx = tid + i * 256, r = idx >> 3, q = idx & 7;
                cp16(sbase + (uint32_t)(nb * 128 * 36 + r * 36 + q * 4) * 4,
                     Ab + (size_t)r * K + q * 4);
            }
            const float* Bb = Bg + (ck + 1) * 32;
#pragma unroll
            for (int i = 0; i < BN / 32; i++) {
                int idx = tid + i * 256, r = idx >> 3, q = idx & 7;
                cp16(sbase + BOFF + (uint32_t)(nb * BN * 36 + r * 36 + q * 4) * 4,
                     Bb + (size_t)r * K + q * 4);
            }
            cp_commit();
            cp_wait<1>();
        } else {
            cp_wait<0>();
        }
        __syncthreads();

        const float* Ab = As + buf * 128 * 36;
        const float* Bb = Bs + buf * BN * 36;
#pragma unroll
        for (int s = 0; s < 4; s++) {
            const int k = s * 8;
            uint32_t ah[MF][4], al[MF][4], bh[4][2], bl[4][2];
#pragma unroll
            for (int mf = 0; mf < MF; mf++) {
                const float* ap = Ab + (m0w + mf * 16 + g) * 36 + k + tig;
                tf32_split(ap[0],          ah[mf][0], al[mf][0]);
                tf32_split(ap[8 * 36],     ah[mf][1], al[mf][1]);
                tf32_split(ap[4],          ah[mf][2], al[mf][2]);
                tf32_split(ap[8 * 36 + 4], ah[mf][3], al[mf][3]);
            }
#pragma unroll
            for (int nf = 0; nf < 4; nf++) {
                const float* bp = Bb + (n0w + nf * 8 + g) * 36 + k + tig;
                tf32_split(bp[0], bh[nf][0], bl[nf][0]);
                tf32_split(bp[4], bh[nf][1], bl[nf][1]);
            }
            // 3xTF32: hi*hi + hi*lo + lo*hi (lo*lo dropped, ~2^-22)
#pragma unroll
            for (int mf = 0; mf < MF; mf++)
#pragma unroll
                for (int nf = 0; nf < 4; nf++) {
                    mma8(acc[mf][nf], al[mf], bh[nf]);
                    mma8(acc[mf][nf], ah[mf], bl[nf]);
                    mma8(acc[mf][nf], ah[mf], bh[nf]);
                }
        }
        __syncthreads();
    }

    // ------------------------------ epilogue --------------------------------
#pragma unroll
    for (int mf = 0; mf < MF; mf++) {
        const int r0 = m0 + m0w + mf * 16 + g;
        const int r1 = r0 + 8;
#pragma unroll
        for (int nf = 0; nf < 4; nf++) {
            const int col = n0 + n0w + nf * 8 + tig * 2;
            if (EPI == 3) {
#pragma unroll
                for (int half = 0; half < 2; half++) {
                    const int row = half ? r1 : r0;
                    const int n = row >> (2 * wsh);
                    const int rem = row & ((1 << (2 * wsh)) - 1);
                    const int h = rem >> wsh, w = rem & ((1 << wsh) - 1);
#pragma unroll
                    for (int e = 0; e < 2; e++) {
                        const int c = col + e;
                        const int o = c >> 2, a = (c >> 1) & 1, b = c & 1;
                        size_t pix = ((size_t)n << (2 * wsh + 2))
                                   + (size_t)((2 * h + a) << (wsh + 1)) + 2 * w + b;
                        size_t adr = pix * Cout + o;
                        Cp[adr] = acc[mf][nf][half * 2 + e] + Base[adr];
                    }
                }
            } else {
                size_t off0 = (size_t)r0 * Ntot + col;
                size_t off1 = (size_t)r1 * Ntot + col;
                float2 v0 = make_float2(acc[mf][nf][0], acc[mf][nf][1]);
                float2 v1 = make_float2(acc[mf][nf][2], acc[mf][nf][3]);
                if (EPI == 0) {
                    v0.x = fmaxf(v0.x, 0.f); v0.y = fmaxf(v0.y, 0.f);
                    v1.x = fmaxf(v1.x, 0.f); v1.y = fmaxf(v1.y, 0.f);
                } else if (EPI == 1) {
                    float2 b0 = *(const float2*)(Base + off0);
                    float2 b1 = *(const float2*)(Base + off1);
                    v0.x += b0.x; v0.y += b0.y;
                    v1.x += b1.x; v1.y += b1.y;
                }
                *(float2*)(Cp + off0) = v0;
                *(float2*)(Cp + off1) = v1;
            }
        }
    }
}

// ------------------------- depthwise 7x7 (NHWC) -----------------------------
__device__ __forceinline__ void f4fma(float4& a, float4 w, float4 x) {
    a.x += w.x * x.x; a.y += w.y * x.y; a.z += w.z * x.z; a.w += w.w * x.w;
}
__global__ __launch_bounds__(256, 3) void dw7_nhwc(
    const float* __restrict__ x, const float* __restrict__ wT,
    float* __restrict__ y, int C, int H, int W, int total)
{
    int idx = blockIdx.x * blockDim.x + threadIdx.x;
    if (idx >= total) return;
    const int C4 = C >> 2;
    int c4 = idx % C4;
    int t = idx / C4;
    int w4 = t % (W >> 2); t /= (W >> 2);
    int h = t % H;
    int n = t / H;
    int w0 = w4 * 4;
    const float* xb = x + (size_t)n * H * W * C + (size_t)c4 * 4;
    float4 acc[4];
#pragma unroll
    for (int j = 0; j < 4; j++) acc[j] = make_float4(0.f, 0.f, 0.f, 0.f);

    const bool interior = (h >= 3) & (h < H - 3) & (w0 >= 4) & (w0 <= W - 8);
    if (interior) {
        const float* xc = xb + ((size_t)(h - 3) * W + (w0 - 3)) * C;
#pragma unroll
        for (int dy = 0; dy < 7; dy++) {
            const float* xrow = xc + (size_t)dy * W * C;
            float4 wv[7];
#pragma unroll
            for (int k = 0; k < 7; k++)
                wv[k] = *(const float4*)(wT + (size_t)(dy * 7 + k) * C + c4 * 4);
#pragma unroll
            for (int dx = 0; dx < 10; dx++) {
                float4 xv = *(const float4*)(xrow + (size_t)dx * C);
#pragma unroll
                for (int j = 0; j < 4; j++) {
                    int k = dx - j;
                    if (k >= 0 && k < 7) f4fma(acc[j], wv[k], xv);
                }
            }
        }
    } else {
        for (int dy = 0; dy < 7; dy++) {
            int hy = h + dy - 3;
            if ((unsigned)hy >= (unsigned)H) continue;
            const float* xrow = xb + (size_t)hy * W * C;
            float4 wv[7];
#pragma unroll
            for (int k = 0; k < 7; k++)
                wv[k] = *(const float4*)(wT + (size_t)(dy * 7 + k) * C + c4 * 4);
#pragma unroll
            for (int dx = 0; dx < 10; dx++) {
                int wx = w0 + dx - 3;
                if ((unsigned)wx >= (unsigned)W) continue;
                float4 xv = *(const float4*)(xrow + (size_t)wx * C);
#pragma unroll
                for (int j = 0; j < 4; j++) {
                    int k = dx - j;
                    if (k >= 0 && k < 7) f4fma(acc[j], wv[k], xv);
                }
            }
        }
    }
    float* yb = y + ((size_t)(n * H + h) * W + w0) * C + c4 * 4;
#pragma unroll
    for (int j = 0; j < 4; j++) *(float4*)(yb + (size_t)j * C) = acc[j];
}

// --------------------------- weight prep ------------------------------------
__global__ void dwT2_k(const float* __restrict__ dw, float* __restrict__ o,
                       int C, int total) {
    int idx = blockIdx.x * blockDim.x + threadIdx.x;
    if (idx >= total) return;
    int b = idx / (49 * C), r = idx % (49 * C);
    int tap = r / C, c = r % C;
    o[idx] = dw[(size_t)b * C * 49 + c * 49 + tap];
}
__global__ void wheadT_k(const float* __restrict__ w, float* __restrict__ o) {
    int idx = blockIdx.x * blockDim.x + threadIdx.x;
    if (idx >= 576) return;
    int tap = idx / 64, oc = idx % 64;
    o[idx] = w[oc * 9 + tap];
}
__global__ void wtailT_k(const float* __restrict__ w, float* __restrict__ o) {
    int idx = blockIdx.x * blockDim.x + threadIdx.x;
    if (idx >= 1152) return;
    int oc = idx / 576, r = idx % 576;
    int tap = r / 64, c = r % 64;
    o[oc * 576 + tap * 64 + c] = w[(oc * 64 + c) * 9 + tap];
}
__global__ void wdnR_k(const float* __restrict__ w, float* __restrict__ o,
                       int Ci, int total) {
    int idx = blockIdx.x * blockDim.x + threadIdx.x;
    if (idx >= total) return;
    int K4 = 4 * Ci;
    int co = idx / K4, k = idx % K4;
    int ab = k / Ci, ci = k % Ci;
    o[idx] = w[(size_t)co * K4 + ci * 4 + ab];
}
__global__ void wupT_k(const float* __restrict__ w, float* __restrict__ o,
                       int Ci, int M, int total) {
    int idx = blockIdx.x * blockDim.x + threadIdx.x;
    if (idx >= total) return;
    int ci = idx % Ci, m = idx / Ci;
    o[idx] = w[(size_t)ci * M + m];
}

// ----------------------- space-to-depth (NHWC, ab-major K) ------------------
__global__ void s2d_k(const float* __restrict__ x, float* __restrict__ o,
                      int Ci, int Ho, int Wo, int total)
{
    int idx = blockIdx.x * blockDim.x + threadIdx.x;
    if (idx >= total) return;
    const int Ci4 = Ci >> 2;
    int ci4 = idx % Ci4;
    int t = idx / Ci4;
    int ab = t & 3; t >>= 2;
    int wo = t % Wo; t /= Wo;
    int ho = t % Ho;
    int n = t / Ho;
    int a = ab >> 1, bq = ab & 1;
    int Wi = 2 * Wo;
    float4 v = *(const float4*)(x
        + ((size_t)(n * 2 * Ho + 2 * ho + a) * Wi + 2 * wo + bq) * Ci + ci4 * 4);
    *(float4*)(o + ((size_t)((n * Ho + ho) * Wo + wo)) * 4 * Ci
               + (size_t)ab * Ci + ci4 * 4) = v;
}

// ------------------------------ head / tail ---------------------------------
__global__ void head_k(const float* __restrict__ x0, const float* __restrict__ wT,
                       float* __restrict__ y, int total)
{
    int idx = blockIdx.x * blockDim.x + threadIdx.x;
    if (idx >= total) return;
    int o4 = idx & 15;
    int p = idx >> 4;
    int hw = p & 65535, n = p >> 16;
    int h = hw >> 8, w = hw & 255;
    const float* xp = x0 + (size_t)n * 65536;
    float4 acc = make_float4(0.f, 0.f, 0.f, 0.f);
#pragma unroll
    for (int dy = 0; dy < 3; dy++) {
        int yy = h + dy - 1;
        if ((unsigned)yy >= 256u) continue;
#pragma unroll
        for (int dx = 0; dx < 3; dx++) {
            int xx = w + dx - 1;
            if ((unsigned)xx >= 256u) continue;
            float xv = xp[yy * 256 + xx];
            float4 wv = *(const float4*)(wT + (dy * 3 + dx) * 64 + o4 * 4);
            acc.x += xv * wv.x; acc.y += xv * wv.y;
            acc.z += xv * wv.z; acc.w += xv * wv.w;
        }
    }
    *(float4*)(y + (size_t)p * 64 + o4 * 4) = acc;
}

__global__ void tail_k(const float* __restrict__ x, const float* __restrict__ wt,
                       float* __restrict__ T, int total)
{
    int idx = blockIdx.x * blockDim.x + threadIdx.x;
    if (idx >= total) return;
    int n = idx >> 16, hw = idx & 65535;
    int h = hw >> 8, w = hw & 255;
    const float* xn = x + (size_t)n * 65536 * 64;
    float a0 = 0.f, a1 = 0.f;
    for (int dy = 0; dy < 3; dy++) {
        int yy = h + dy - 1;
        if ((unsigned)yy >= 256u) continue;
        for (int dx = 0; dx < 3; dx++) {
            int xx = w + dx - 1;
            if ((unsigned)xx >= 256u) continue;
            int tap = dy * 3 + dx;
            const float* xp = xn + ((size_t)yy * 256 + xx) * 64;
            const float* w0p = wt + tap * 64;
            const float* w1p = wt + 576 + tap * 64;
#pragma unroll
            for (int c4 = 0; c4 < 16; c4++) {
                float4 xv = *(const float4*)(xp + c4 * 4);
                float4 w0 = *(const float4*)(w0p + c4 * 4);
                float4 w1 = *(const float4*)(w1p + c4 * 4);
                a0 += xv.x * w0.x + xv.y * w0.y + xv.z * w0.z + xv.w * w0.w;
                a1 += xv.x * w1.x + xv.y * w1.y + xv.z * w1.z + xv.w * w1.w;
            }
        }
    }
    T[(size_t)n * 131072 + hw] = a0;
    T[(size_t)n * 131072 + 65536 + hw] = a1;
}

// ------------------------------ epilogue ------------------------------------
__global__ void mean1_k(const float* __restrict__ tail, float* __restrict__ ps)
{
    __shared__ float s[256];
    int n = blockIdx.x, j = blockIdx.y;
    const float* p = tail + (size_t)n * 131072 + j * 2048;
    float acc = 0.f;
    for (int i = threadIdx.x; i < 2048; i += 256) acc += p[i];
    s[threadIdx.x] = acc;
    __syncthreads();
    for (int st = 128; st > 0; st >>= 1) {
        if (threadIdx.x < st) s[threadIdx.x] += s[threadIdx.x + st];
        __syncthreads();
    }
    if (threadIdx.x == 0) ps[n * 32 + j] = s[0];
}
__global__ void mean2_k(const float* __restrict__ ps, float* __restrict__ mean)
{
    int t = threadIdx.x;
    if (t < NBATCH) {
        float s = 0.f;
        for (int j = 0; j < 32; j++) s += ps[t * 32 + j];
        mean[t] = s * (1.f / 65536.f);
    }
}

__global__ void finalize1(const float* __restrict__ tail, const float* __restrict__ x0,
                          const float* __restrict__ mean, float* __restrict__ out,
                          float* __restrict__ u)
{
    int idx = blockIdx.x * blockDim.x + threadIdx.x;
    if (idx >= 524288) return;
    int n = idx >> 16, p = idx & 65535;
    float nd = tail[(size_t)n * 131072 + 65536 + p];
    out[idx] = mean[n];
    out[524288 + idx] = nd;
    u[idx] = nd + x0[idx];
}

__device__ __forceinline__ float gx_(const float* u, int h, int w) {
    if (w == 0)   return u[h * 256 + 1] - u[h * 256];
    if (w == 255) return u[h * 256 + 255] - u[h * 256 + 254];
    return 0.5f * (u[h * 256 + w + 1] - u[h * 256 + w - 1]);
}
__device__ __forceinline__ float gy_(const float* u, int h, int w) {
    if (h == 0)   return u[256 + w] - u[w];
    if (h == 255) return u[255 * 256 + w] - u[254 * 256 + w];
    return 0.5f * (u[(h + 1) * 256 + w] - u[(h - 1) * 256 + w]);
}

__global__ void grad_k(const float* __restrict__ u, float* __restrict__ ux,
                       float* __restrict__ uy)
{
    int idx = blockIdx.x * blockDim.x + threadIdx.x;
    if (idx >= 524288) return;
    int n = idx >> 16, p = idx & 65535;
    int h = p >> 8, w = p & 255;
    const float* up = u + (size_t)n * 65536;
    ux[idx] = gx_(up, h, w);
    uy[idx] = gy_(up, h, w);
}

__global__ void curv_k(const float* __restrict__ ux, const float* __restrict__ uy,
                       float* __restrict__ out)
{
    int idx = blockIdx.x * blockDim.x + threadIdx.x;
    if (idx >= 524288) return;
    int n = idx >> 16, p = idx & 65535;
    int h = p >> 8, w = p & 255;
    const float* uxp = ux + (size_t)n * 65536;
    const float* uyp = uy + (size_t)n * 65536;
    float uxx = gx_(uxp, h, w);
    float uyy = gy_(uyp, h, w);
    float uxy = gy_(uxp, h, w);
    float a = uxp[h * 256 + w], b = uyp[h * 256 + w];
    float den = 1.f + a * a + b * b;
    out[idx] = (uxx * uyy - uxy * uxy) / (den * den);
}

// ------------------------------ host side -----------------------------------
static inline int ceil_div(int a, int b) { return (a + b - 1) / b; }
static inline int smszA(int bn) { return (2 * 128 * 36 + 2 * bn * 36) * 4; }

static void run_stage(const float* dwW, const float* w1, const float* w2,
                      float* x, float* hbuf, float* ebuf, float* wdwT,
                      int C, int H, int W)
{
    int P = H * W, rows = NBATCH * P, tiles = rows / 128;
    int dwtot = 2 * 49 * C;
    dwT2_k<<<ceil_div(dwtot, 256), 256>>>(dwW, wdwT, C, dwtot);
    int dwthr = NBATCH * H * (W / 4) * (C / 4);
    for (int b = 0; b < 2; b++) {
        dw7_nhwc<<<ceil_div(dwthr, 256), 256>>>(x, wdwT + b * 49 * C, hbuf, C, H, W, dwthr);
        mma_gemm<128, 0><<<dim3((4 * C) / 128, tiles), 256, smszA(128)>>>(
            hbuf, w1 + (size_t)b * 4 * C * C, ebuf, ebuf, C, 4 * C, 0, 0);
        const float* w2b = w2 + (size_t)b * C * 4 * C;
        if (C == 64)
            mma_gemm<64, 1><<<dim3(1, tiles), 256, smszA(64)>>>(
                ebuf, w2b, x, x, 4 * C, C, 0, 0);
        else
            mma_gemm<128, 1><<<dim3(C / 128, tiles), 256, smszA(128)>>>(
                ebuf, w2b, x, x, 4 * C, C, 0, 0);
    }
}

static void run_down(const float* x, const float* wdn, float* hbuf, float* wd,
                     float* y, int Ci, int Co, int Ho, int Wo)
{
    int K = 4 * Ci;
    int wtot = Co * K;
    wdnR_k<<<ceil_div(wtot, 256), 256>>>(wdn, wd, Ci, wtot);
    int s2dtot = NBATCH * Ho * Wo * 4 * (Ci / 4);
    s2d_k<<<ceil_div(s2dtot, 256), 256>>>(x, hbuf, Ci, Ho, Wo, s2dtot);
    int tiles = NBATCH * Ho * Wo / 128;
    mma_gemm<128, 2><<<dim3(Co / 128, tiles), 256, smszA(128)>>>(
        hbuf, wd, y, y, K, Co, 0, 0);
}

static void run_up(const float* x, const float* wup, const float* skip, float* y,
                   float* wt, int Ci, int Co, int wsh)
{
    int M = Co * 4;
    int wtot = M * Ci;
    wupT_k<<<ceil_div(wtot, 256), 256>>>(wup, wt, Ci, M, wtot);
    int P_lo = 1 << (2 * wsh);
    int tiles = NBATCH * P_lo / 128;
    mma_gemm<128, 3><<<dim3(M / 128, tiles), 256, smszA(128)>>>(
        x, wt, y, skip, Ci, M, wsh, Co);
}

extern "C" void kernel_launch(void* const* d_in, const int* in_sizes, int n_in,
                              void* d_out, int out_size)
{
    const float* x0      = (const float*)d_in[0];
    const float* w_head  = (const float*)d_in[1];
    const float* en1_dw  = (const float*)d_in[2];
    const float* en1_w1  = (const float*)d_in[3];
    const float* en1_w2  = (const float*)d_in[4];
    const float* w_down1 = (const float*)d_in[5];
    const float* en2_dw  = (const float*)d_in[6];
    const float* en2_w1  = (const float*)d_in[7];
    const float* en2_w2  = (const float*)d_in[8];
    const float* w_down2 = (const float*)d_in[9];
    const float* en3_dw  = (const float*)d_in[10];
    const float* en3_w1  = (const float*)d_in[11];
    const float* en3_w2  = (const float*)d_in[12];
    const float* w_down3 = (const float*)d_in[13];
    const float* body_dw = (const float*)d_in[14];
    const float* body_w1 = (const float*)d_in[15];
    const float* body_w2 = (const float*)d_in[16];
    const float* w_up3   = (const float*)d_in[17];
    const float* de3_dw  = (const float*)d_in[18];
    const float* de3_w1  = (const float*)d_in[19];
    const float* de3_w2  = (const float*)d_in[20];
    const float* w_up2   = (const float*)d_in[21];
    const float* de2_dw  = (const float*)d_in[22];
    const float* de2_w1  = (const float*)d_in[23];
    const float* de2_w2  = (const float*)d_in[24];
    const float* w_up1   = (const float*)d_in[25];
    const float* de1_dw  = (const float*)d_in[26];
    const float* de1_w1  = (const float*)d_in[27];
    const float* de1_w2  = (const float*)d_in[28];
    const float* w_tail  = (const float*)d_in[29];
    float* out = (float*)d_out;

    cudaFuncSetAttribute(mma_gemm<128, 0>, cudaFuncAttributeMaxDynamicSharedMemorySize, smszA(128));
    cudaFuncSetAttribute(mma_gemm<128, 1>, cudaFuncAttributeMaxDynamicSharedMemorySize, smszA(128));
    cudaFuncSetAttribute(mma_gemm<64, 1>,  cudaFuncAttributeMaxDynamicSharedMemorySize, smszA(64));
    cudaFuncSetAttribute(mma_gemm<128, 2>, cudaFuncAttributeMaxDynamicSharedMemorySize, smszA(128));
    cudaFuncSetAttribute(mma_gemm<128, 3>, cudaFuncAttributeMaxDynamicSharedMemorySize, smszA(128));

    float *X1, *X2, *X3, *X4, *H, *E, *D3, *D2, *D1, *T, *U, *UX, *UY, *MN, *PS, *WT, *WD, *WDW, *WH, *WTL;
    cudaGetSymbolAddress((void**)&X1, g_x1);
    cudaGetSymbolAddress((void**)&X2, g_x2);
    cudaGetSymbolAddress((void**)&X3, g_x3);
    cudaGetSymbolAddress((void**)&X4, g_x4);
    cudaGetSymbolAddress((void**)&H,  g_h);
    cudaGetSymbolAddress((void**)&E,  g_e);
    cudaGetSymbolAddress((void**)&D3, g_d3);
    cudaGetSymbolAddress((void**)&D2, g_d2);
    cudaGetSymbolAddress((void**)&D1, g_d1);
    cudaGetSymbolAddress((void**)&T,  g_t);
    cudaGetSymbolAddress((void**)&U,  g_u);
    cudaGetSymbolAddress((void**)&UX, g_ux);
    cudaGetSymbolAddress((void**)&UY, g_uy);
    cudaGetSymbolAddress((void**)&MN, g_mn);
    cudaGetSymbolAddress((void**)&PS, g_ps);
    cudaGetSymbolAddress((void**)&WT, g_wt);
    cudaGetSymbolAddress((void**)&WD, g_wd);
    cudaGetSymbolAddress((void**)&WDW, g_wdw);
    cudaGetSymbolAddress((void**)&WH, g_wh);
    cudaGetSymbolAddress((void**)&WTL, g_wtl);

    // ---------------- encoder (NHWC) ----------------
    wheadT_k<<<3, 256>>>(w_head, WH);
    {
        int total = NBATCH * 65536 * 16;
        head_k<<<ceil_div(total, 256), 256>>>(x0, WH, X1, total);
    }
    run_stage(en1_dw, en1_w1, en1_w2, X1, H, E, WDW, 64, 256, 256);

    run_down(X1, w_down1, H, WD, X2, 64, 128, 128, 128);
    run_stage(en2_dw, en2_w1, en2_w2, X2, H, E, WDW, 128, 128, 128);

    run_down(X2, w_down2, H, WD, X3, 128, 256, 64, 64);
    run_stage(en3_dw, en3_w1, en3_w2, X3, H, E, WDW, 256, 64, 64);

    run_down(X3, w_down3, H, WD, X4, 256, 512, 32, 32);
    run_stage(body_dw, body_w1, body_w2, X4, H, E, WDW, 512, 32, 32);

    // ---------------- decoder ----------------
    run_up(X4, w_up3, X3, D3, WT, 512, 256, 5);
    run_stage(de3_dw, de3_w1, de3_w2, D3, H, E, WDW, 256, 64, 64);

    run_up(D3, w_up2, X2, D2, WT, 256, 128, 6);
    run_stage(de2_dw, de2_w1, de2_w2, D2, H, E, WDW, 128, 128, 128);

    run_up(D2, w_up1, X1, D1, WT, 128, 64, 7);
    run_stage(de1_dw, de1_w1, de1_w2, D1, H, E, WDW, 64, 256, 256);

    wtailT_k<<<5, 256>>>(w_tail, WTL);
    {
        int total = NBATCH * 65536;
        tail_k<<<ceil_div(total, 256), 256>>>(D1, WTL, T, total);
    }

    // ---------------- epilogue ----------------
    mean1_k<<<dim3(NBATCH, 32), 256>>>(T, PS);
    mean2_k<<<1, 32>>>(PS, MN);
    finalize1<<<2048, 256>>>(T, x0, MN, out, U);
    grad_k<<<2048, 256>>>(U, UX, UY);
    curv_k<<<2048, 256>>>(UX, UY, out + 1048576);
}